// round 1
// baseline (speedup 1.0000x reference)
#include <cuda_runtime.h>
#include <cuda_bf16.h>
#include <cstdint>

// Problem constants
#define BB 2
#define TT 4096
#define EE 768
#define HH 12
#define DD 64
#define MM (BB * TT)        // 8192
#define N_QKV (3 * EE)      // 2304

// Scratch (allocation-free rule: __device__ globals)
__device__ float g_q[(size_t)BB * HH * TT * DD];
__device__ float g_k[(size_t)BB * HH * TT * DD];
__device__ float g_v[(size_t)BB * HH * TT * DD];
__device__ float g_y[(size_t)BB * TT * EE];

// ---------------------------------------------------------------------------
// Kernel 1: QKV GEMM.  C[8192,2304] = X[8192,768] @ W[768,2304] + b
// 128x128 tile, 256 threads, 8x8 per thread, Ktile=16.
// Epilogue scatters into g_q/g_k/g_v in [B,H,T,D] layout (free head transpose).
// ---------------------------------------------------------------------------
__global__ __launch_bounds__(256) void qkv_gemm_kernel(
    const float* __restrict__ X, const float* __restrict__ W,
    const float* __restrict__ bias)
{
    __shared__ float As[16][132];   // [k][m], padded row = 132 floats (16B-aligned)
    __shared__ float Bs[16][132];   // [k][n]

    const int tid = threadIdx.x;
    const int tx = tid & 15;
    const int ty = tid >> 4;
    const int m0 = blockIdx.y * 128;
    const int n0 = blockIdx.x * 128;

    float acc[8][8];
#pragma unroll
    for (int i = 0; i < 8; i++)
#pragma unroll
        for (int j = 0; j < 8; j++) acc[i][j] = 0.f;

    for (int k0 = 0; k0 < EE; k0 += 16) {
        // Load X tile (128 rows x 16 k) transposed into As[k][m]
#pragma unroll
        for (int i = 0; i < 2; i++) {
            int f = tid * 2 + i;                // 0..511
            int row = f >> 2;                   // 0..127
            int kq = (f & 3) * 4;               // 0,4,8,12
            float4 xv = *(const float4*)&X[(size_t)(m0 + row) * EE + k0 + kq];
            As[kq + 0][row] = xv.x;
            As[kq + 1][row] = xv.y;
            As[kq + 2][row] = xv.z;
            As[kq + 3][row] = xv.w;
        }
        // Load W tile (16 k x 128 n) into Bs[k][n]
#pragma unroll
        for (int i = 0; i < 2; i++) {
            int f = tid * 2 + i;
            int kr = f >> 5;                    // 0..15
            int c4 = (f & 31) * 4;              // 0..124
            float4 wv = *(const float4*)&W[(size_t)(k0 + kr) * N_QKV + n0 + c4];
            *(float4*)&Bs[kr][c4] = wv;
        }
        __syncthreads();

#pragma unroll
        for (int kk = 0; kk < 16; kk++) {
            float4 a0 = *(float4*)&As[kk][ty * 4];
            float4 a1 = *(float4*)&As[kk][64 + ty * 4];
            float4 b0 = *(float4*)&Bs[kk][tx * 4];
            float4 b1 = *(float4*)&Bs[kk][64 + tx * 4];
            float a[8] = {a0.x, a0.y, a0.z, a0.w, a1.x, a1.y, a1.z, a1.w};
            float b[8] = {b0.x, b0.y, b0.z, b0.w, b1.x, b1.y, b1.z, b1.w};
#pragma unroll
            for (int i = 0; i < 8; i++)
#pragma unroll
                for (int j = 0; j < 8; j++) acc[i][j] += a[i] * b[j];
        }
        __syncthreads();
    }

    // Epilogue: bias + scatter to Q/K/V head-major [B,H,T,D]
#pragma unroll
    for (int i = 0; i < 8; i++) {
        int ml = (i < 4) ? (ty * 4 + i) : (64 + ty * 4 + (i - 4));
        int gm = m0 + ml;
        int bb = gm >> 12;       // / TT
        int t = gm & (TT - 1);
#pragma unroll
        for (int j = 0; j < 8; j++) {
            int nl = (j < 4) ? (tx * 4 + j) : (64 + tx * 4 + (j - 4));
            int gn = n0 + nl;
            float v = acc[i][j] + bias[gn];
            int part = gn / EE;
            int rem = gn - part * EE;
            int h = rem >> 6;
            int d = rem & 63;
            float* dst = (part == 0) ? g_q : ((part == 1) ? g_k : g_v);
            dst[((((size_t)bb * HH + h) * TT) + t) * DD + d] = v;
        }
    }
}

// ---------------------------------------------------------------------------
// Kernel 2: causal flash attention (fp32, online softmax).
// Grid: (T/64, H, B). 256 threads. Br=Bc=64, D=64.
// Per KV tile: S = Q K^T (64x64x64), online softmax, O += P V (64x64x64).
// Only the diagonal tile applies the causal mask; later tiles are skipped.
// ---------------------------------------------------------------------------
#define FPAD 68   // padded row stride (floats); 68*4=272 bytes, 16B aligned

extern __shared__ float fa_smem[];

__global__ __launch_bounds__(256) void flash_attn_kernel()
{
    float* Qs = fa_smem;              // [d][m]  64 x FPAD
    float* Ks = Qs + 64 * FPAD;       // [d][n]
    float* Vs = Ks + 64 * FPAD;       // [n][j]
    float* Ps = Vs + 64 * FPAD;       // [n][m]
    float* red = Ps + 64 * FPAD;      // [64][16] reduction scratch

    const int tid = threadIdx.x;
    const int tx = tid & 15;
    const int ty = tid >> 4;
    const int qt = blockIdx.x;
    const int h = blockIdx.y;
    const int bb = blockIdx.z;
    const int q_lo = qt * 64;

    const size_t head_off = (((size_t)bb * HH + h) * TT) * DD;
    const float* qbase = g_q + head_off;
    const float* kbase = g_k + head_off;
    const float* vbase = g_v + head_off;

    // Load Q tile transposed into Qs[d][m]
#pragma unroll
    for (int i = 0; i < 4; i++) {
        int f = tid * 4 + i;               // 0..1023
        int row = f >> 4;                  // 0..63
        int dq = (f & 15) * 4;             // 0..60
        float4 qv = *(const float4*)&qbase[(size_t)(q_lo + row) * DD + dq];
        Qs[(dq + 0) * FPAD + row] = qv.x;
        Qs[(dq + 1) * FPAD + row] = qv.y;
        Qs[(dq + 2) * FPAD + row] = qv.z;
        Qs[(dq + 3) * FPAD + row] = qv.w;
    }

    float o_acc[4][4];
    float m_prev[4], l_run[4];
#pragma unroll
    for (int i = 0; i < 4; i++) {
        m_prev[i] = -1e30f;
        l_run[i] = 0.f;
#pragma unroll
        for (int j = 0; j < 4; j++) o_acc[i][j] = 0.f;
    }
    const float scale = 0.125f;  // 1/sqrt(64)

    for (int kt = 0; kt <= qt; kt++) {
        __syncthreads();   // prior iter's P·V reads of Vs/Ps done; Q load visible (iter 0)

        // Load K (transposed) and V (direct) tiles
#pragma unroll
        for (int i = 0; i < 4; i++) {
            int f = tid * 4 + i;
            int row = f >> 4;
            int dq = (f & 15) * 4;
            float4 kv = *(const float4*)&kbase[(size_t)(kt * 64 + row) * DD + dq];
            Ks[(dq + 0) * FPAD + row] = kv.x;
            Ks[(dq + 1) * FPAD + row] = kv.y;
            Ks[(dq + 2) * FPAD + row] = kv.z;
            Ks[(dq + 3) * FPAD + row] = kv.w;
            float4 vv = *(const float4*)&vbase[(size_t)(kt * 64 + row) * DD + dq];
            *(float4*)&Vs[row * FPAD + dq] = vv;
        }
        __syncthreads();

        // S = Q K^T  (4x4 per thread)
        float s[4][4];
#pragma unroll
        for (int i = 0; i < 4; i++)
#pragma unroll
            for (int j = 0; j < 4; j++) s[i][j] = 0.f;

#pragma unroll
        for (int kd = 0; kd < 64; kd++) {
            float4 a = *(float4*)&Qs[kd * FPAD + ty * 4];
            float4 b = *(float4*)&Ks[kd * FPAD + tx * 4];
            float av[4] = {a.x, a.y, a.z, a.w};
            float bv[4] = {b.x, b.y, b.z, b.w};
#pragma unroll
            for (int i = 0; i < 4; i++)
#pragma unroll
                for (int j = 0; j < 4; j++) s[i][j] += av[i] * bv[j];
        }

        // Scale + causal mask (diag tile only)
        const bool diag = (kt == qt);
#pragma unroll
        for (int i = 0; i < 4; i++) {
            int grow = q_lo + ty * 4 + i;
#pragma unroll
            for (int j = 0; j < 4; j++) {
                float v = s[i][j] * scale;
                if (diag) {
                    int gcol = kt * 64 + tx * 4 + j;
                    if (gcol > grow) v = -1e30f;
                }
                s[i][j] = v;
            }
        }

        // Row max (partial -> shared -> full)
#pragma unroll
        for (int i = 0; i < 4; i++) {
            float mx = fmaxf(fmaxf(s[i][0], s[i][1]), fmaxf(s[i][2], s[i][3]));
            red[(ty * 4 + i) * 16 + tx] = mx;
        }
        __syncthreads();
        float mnew[4], fac[4];
#pragma unroll
        for (int i = 0; i < 4; i++) {
            float mx = m_prev[i];
            const float* rr = &red[(ty * 4 + i) * 16];
#pragma unroll
            for (int t2 = 0; t2 < 16; t2++) mx = fmaxf(mx, rr[t2]);
            mnew[i] = mx;
            fac[i] = __expf(m_prev[i] - mx);
            m_prev[i] = mx;
        }
        __syncthreads();

        // P = exp(S - m), write P transposed to shared, partial row sums
#pragma unroll
        for (int i = 0; i < 4; i++) {
            float sum = 0.f;
#pragma unroll
            for (int j = 0; j < 4; j++) {
                float p = __expf(s[i][j] - mnew[i]);
                sum += p;
                Ps[(tx * 4 + j) * FPAD + (ty * 4 + i)] = p;
            }
            red[(ty * 4 + i) * 16 + tx] = sum;
        }
        __syncthreads();
#pragma unroll
        for (int i = 0; i < 4; i++) {
            float sm = 0.f;
            const float* rr = &red[(ty * 4 + i) * 16];
#pragma unroll
            for (int t2 = 0; t2 < 16; t2++) sm += rr[t2];
            l_run[i] = l_run[i] * fac[i] + sm;
#pragma unroll
            for (int j = 0; j < 4; j++) o_acc[i][j] *= fac[i];
        }

        // O += P V
#pragma unroll
        for (int kn = 0; kn < 64; kn++) {
            float4 a = *(float4*)&Ps[kn * FPAD + ty * 4];
            float4 b = *(float4*)&Vs[kn * FPAD + tx * 4];
            float av[4] = {a.x, a.y, a.z, a.w};
            float bv[4] = {b.x, b.y, b.z, b.w};
#pragma unroll
            for (int i = 0; i < 4; i++)
#pragma unroll
                for (int j = 0; j < 4; j++) o_acc[i][j] += av[i] * bv[j];
        }
    }

    // Normalize and write to g_y in [B,T,E] layout (col = h*64 + d)
#pragma unroll
    for (int i = 0; i < 4; i++) {
        int row = q_lo + ty * 4 + i;
        float inv = 1.f / l_run[i];
        float4 o;
        o.x = o_acc[i][0] * inv;
        o.y = o_acc[i][1] * inv;
        o.z = o_acc[i][2] * inv;
        o.w = o_acc[i][3] * inv;
        *(float4*)&g_y[((size_t)bb * TT + row) * EE + h * DD + tx * 4] = o;
    }
}

// ---------------------------------------------------------------------------
// Kernel 3: output projection.  out[8192,768] = Y[8192,768] @ Wp[768,768] + bp
// Same 128x128 tiling as kernel 1.
// ---------------------------------------------------------------------------
__global__ __launch_bounds__(256) void proj_gemm_kernel(
    const float* __restrict__ W, const float* __restrict__ bias,
    float* __restrict__ out)
{
    __shared__ float As[16][132];
    __shared__ float Bs[16][132];

    const int tid = threadIdx.x;
    const int tx = tid & 15;
    const int ty = tid >> 4;
    const int m0 = blockIdx.y * 128;
    const int n0 = blockIdx.x * 128;

    float acc[8][8];
#pragma unroll
    for (int i = 0; i < 8; i++)
#pragma unroll
        for (int j = 0; j < 8; j++) acc[i][j] = 0.f;

    for (int k0 = 0; k0 < EE; k0 += 16) {
#pragma unroll
        for (int i = 0; i < 2; i++) {
            int f = tid * 2 + i;
            int row = f >> 2;
            int kq = (f & 3) * 4;
            float4 xv = *(const float4*)&g_y[(size_t)(m0 + row) * EE + k0 + kq];
            As[kq + 0][row] = xv.x;
            As[kq + 1][row] = xv.y;
            As[kq + 2][row] = xv.z;
            As[kq + 3][row] = xv.w;
        }
#pragma unroll
        for (int i = 0; i < 2; i++) {
            int f = tid * 2 + i;
            int kr = f >> 5;
            int c4 = (f & 31) * 4;
            float4 wv = *(const float4*)&W[(size_t)(k0 + kr) * EE + n0 + c4];
            *(float4*)&Bs[kr][c4] = wv;
        }
        __syncthreads();

#pragma unroll
        for (int kk = 0; kk < 16; kk++) {
            float4 a0 = *(float4*)&As[kk][ty * 4];
            float4 a1 = *(float4*)&As[kk][64 + ty * 4];
            float4 b0 = *(float4*)&Bs[kk][tx * 4];
            float4 b1 = *(float4*)&Bs[kk][64 + tx * 4];
            float a[8] = {a0.x, a0.y, a0.z, a0.w, a1.x, a1.y, a1.z, a1.w};
            float b[8] = {b0.x, b0.y, b0.z, b0.w, b1.x, b1.y, b1.z, b1.w};
#pragma unroll
            for (int i = 0; i < 8; i++)
#pragma unroll
                for (int j = 0; j < 8; j++) acc[i][j] += a[i] * b[j];
        }
        __syncthreads();
    }

#pragma unroll
    for (int i = 0; i < 8; i++) {
        int ml = (i < 4) ? (ty * 4 + i) : (64 + ty * 4 + (i - 4));
        int gm = m0 + ml;
#pragma unroll
        for (int j = 0; j < 8; j++) {
            int nl = (j < 4) ? (tx * 4 + j) : (64 + tx * 4 + (j - 4));
            int gn = n0 + nl;
            out[(size_t)gm * EE + gn] = acc[i][j] + bias[gn];
        }
    }
}

// ---------------------------------------------------------------------------
extern "C" void kernel_launch(void* const* d_in, const int* in_sizes, int n_in,
                              void* d_out, int out_size)
{
    (void)in_sizes; (void)n_in; (void)out_size;
    const float* x      = (const float*)d_in[0];
    const float* W_attn = (const float*)d_in[1];
    const float* b_attn = (const float*)d_in[2];
    const float* W_proj = (const float*)d_in[3];
    const float* b_proj = (const float*)d_in[4];
    float* out = (float*)d_out;

    // 1) QKV projection -> g_q/g_k/g_v ([B,H,T,D])
    qkv_gemm_kernel<<<dim3(N_QKV / 128, MM / 128), 256>>>(x, W_attn, b_attn);

    // 2) Causal flash attention -> g_y ([B,T,E])
    const int fa_smem_bytes = (4 * 64 * FPAD + 64 * 16) * (int)sizeof(float); // 73728
    cudaFuncSetAttribute(flash_attn_kernel,
                         cudaFuncAttributeMaxDynamicSharedMemorySize, fa_smem_bytes);
    flash_attn_kernel<<<dim3(TT / 64, HH, BB), 256, fa_smem_bytes>>>();

    // 3) Output projection -> d_out
    proj_gemm_kernel<<<dim3(EE / 128, MM / 128), 256>>>(W_proj, b_proj, out);
}

// round 2
// speedup vs baseline: 5.5320x; 5.5320x over previous
#include <cuda_runtime.h>
#include <cuda_bf16.h>
#include <cstdint>

// Problem constants
#define BB 2
#define TT 4096
#define EE 768
#define HH 12
#define DD 64
#define MM (BB * TT)        // 8192
#define N_QKV (3 * EE)      // 2304

// Scratch (allocation-free rule: __device__ globals)
__device__ float g_q[(size_t)BB * HH * TT * DD];   // scaled by 1/8 at QKV epilogue
__device__ float g_k[(size_t)BB * HH * TT * DD];
__device__ float g_v[(size_t)BB * HH * TT * DD];
__device__ float g_y[(size_t)BB * TT * EE];

// ---------------------------------------------------------------------------
// tf32 helpers
// ---------------------------------------------------------------------------
__device__ __forceinline__ uint32_t f2tf(float f) {
    uint32_t r;
    asm("cvt.rna.tf32.f32 %0, %1;" : "=r"(r) : "f"(f));
    return r;
}

// m16n8k8 tf32 mma, row.col. Fragment layouts (g=lane>>2, tg=lane&3):
//  A: a0(g,tg) a1(g+8,tg) a2(g,tg+4) a3(g+8,tg+4)
//  B: b0(k=tg,n=g) b1(k=tg+4,n=g)
//  C: c0(g,2tg) c1(g,2tg+1) c2(g+8,2tg) c3(g+8,2tg+1)
__device__ __forceinline__ void mma8(float* c, const uint32_t* a,
                                     uint32_t b0, uint32_t b1) {
    asm volatile(
        "mma.sync.aligned.m16n8k8.row.col.f32.tf32.tf32.f32 "
        "{%0,%1,%2,%3}, {%4,%5,%6,%7}, {%8,%9}, {%0,%1,%2,%3};\n"
        : "+f"(c[0]), "+f"(c[1]), "+f"(c[2]), "+f"(c[3])
        : "r"(a[0]), "r"(a[1]), "r"(a[2]), "r"(a[3]), "r"(b0), "r"(b1));
}

// ---------------------------------------------------------------------------
// Kernel 1: QKV GEMM (tensor core, tf32).
// C[8192,2304] = X[8192,768] @ W[768,2304] + b, scatter to Q/K/V [B,H,T,D].
// Block 128x128, BK=32, 8 warps (4m x 2n), warp tile m32 x n64.
// ---------------------------------------------------------------------------
__global__ __launch_bounds__(256) void qkv_tc_kernel(
    const float* __restrict__ X, const float* __restrict__ W,
    const float* __restrict__ bias)
{
    __shared__ uint32_t As[128][36];   // [m][k], tf32; bank: 4g+tg (conflict-free)
    __shared__ uint32_t Bs[32][136];   // [k][n], tf32; bank: 8tg+g (conflict-free)

    const int tid = threadIdx.x;
    const int warp = tid >> 5, lane = tid & 31;
    const int g = lane >> 2, tg = lane & 3;
    const int wm = warp >> 1, wn = warp & 1;
    const int m0 = blockIdx.y * 128, n0 = blockIdx.x * 128;
    const int m0w = wm * 32, n0w = wn * 64;

    float acc[2][8][4];
#pragma unroll
    for (int mi = 0; mi < 2; mi++)
#pragma unroll
        for (int nt = 0; nt < 8; nt++)
#pragma unroll
            for (int j = 0; j < 4; j++) acc[mi][nt][j] = 0.f;

    const int arow = tid >> 1;
    const int acol = (tid & 1) * 16;
    const int brow = tid >> 3;
    const int bcol = (tid & 7) * 16;

    for (int k0 = 0; k0 < EE; k0 += 32) {
        // A tile: 128x32 from X
#pragma unroll
        for (int j = 0; j < 4; j++) {
            float4 v = *(const float4*)&X[(size_t)(m0 + arow) * EE + k0 + acol + j * 4];
            uint4 u = make_uint4(f2tf(v.x), f2tf(v.y), f2tf(v.z), f2tf(v.w));
            *(uint4*)&As[arow][acol + j * 4] = u;
        }
        // B tile: 32x128 from W
#pragma unroll
        for (int j = 0; j < 4; j++) {
            float4 v = *(const float4*)&W[(size_t)(k0 + brow) * N_QKV + n0 + bcol + j * 4];
            uint4 u = make_uint4(f2tf(v.x), f2tf(v.y), f2tf(v.z), f2tf(v.w));
            *(uint4*)&Bs[brow][bcol + j * 4] = u;
        }
        __syncthreads();

#pragma unroll
        for (int ks = 0; ks < 4; ks++) {
            uint32_t af[2][4];
#pragma unroll
            for (int mi = 0; mi < 2; mi++) {
                int r0 = m0w + mi * 16 + g;
                af[mi][0] = As[r0][tg + 8 * ks];
                af[mi][1] = As[r0 + 8][tg + 8 * ks];
                af[mi][2] = As[r0][tg + 4 + 8 * ks];
                af[mi][3] = As[r0 + 8][tg + 4 + 8 * ks];
            }
#pragma unroll
            for (int nt = 0; nt < 8; nt++) {
                uint32_t b0 = Bs[tg + 8 * ks][n0w + nt * 8 + g];
                uint32_t b1 = Bs[tg + 4 + 8 * ks][n0w + nt * 8 + g];
                mma8(acc[0][nt], af[0], b0, b1);
                mma8(acc[1][nt], af[1], b0, b1);
            }
        }
        __syncthreads();
    }

    // Epilogue: bias, scatter to q/k/v head-major; q gets 1/sqrt(D)=0.125 folded in
#pragma unroll
    for (int mi = 0; mi < 2; mi++)
#pragma unroll
        for (int hi = 0; hi < 2; hi++) {
            int gm = m0 + m0w + mi * 16 + hi * 8 + g;
            int bbv = gm >> 12;
            int t = gm & (TT - 1);
#pragma unroll
            for (int nt = 0; nt < 8; nt++) {
                int gn = n0 + n0w + nt * 8 + 2 * tg;
                float v0 = acc[mi][nt][hi * 2] + bias[gn];
                float v1 = acc[mi][nt][hi * 2 + 1] + bias[gn + 1];
                int part = gn / EE;
                int rem = gn - part * EE;
                int hh = rem >> 6, d = rem & 63;
                float* dst = (part == 0) ? g_q : ((part == 1) ? g_k : g_v);
                float sc = (part == 0) ? 0.125f : 1.0f;
                *(float2*)&dst[(((size_t)bbv * HH + hh) * TT + t) * DD + d] =
                    make_float2(v0 * sc, v1 * sc);
            }
        }
}

// ---------------------------------------------------------------------------
// Kernel 2: causal flash attention (tf32 tensor core, online softmax).
// Grid: (T/128, H, B), 128 threads (4 warps), warp = m32 rows x full n.
// Br=128, Bc=64, D=64. Q frags register-resident; P via smem.
// ---------------------------------------------------------------------------
#define KS_STRIDE 68
#define VS_STRIDE 72
#define PS_STRIDE 68
#define ATT_SMEM_U32 (64 * KS_STRIDE + 64 * VS_STRIDE + 128 * PS_STRIDE)

extern __shared__ uint32_t att_smem[];

__global__ __launch_bounds__(128) void attn_tc_kernel()
{
    uint32_t* Ks = att_smem;                    // [64][68] tf32 K tile [kv][d]
    uint32_t* Vs = Ks + 64 * KS_STRIDE;         // [64][72] tf32 V tile [kv][d]
    uint32_t* Ps = Vs + 64 * VS_STRIDE;         // [128][68] tf32 P tile [row][kv]
    float* Pf = (float*)Ps;                     // staging view for Q load

    const int tid = threadIdx.x;
    const int warp = tid >> 5, lane = tid & 31;
    const int g = lane >> 2, tg = lane & 3;
    const int qt = blockIdx.x, h = blockIdx.y, bb = blockIdx.z;
    const int q0 = qt * 128;
    const int m0w = warp * 32;

    const size_t base = ((size_t)bb * HH + h) * TT * DD;
    const float* qp = g_q + base;
    const float* kp = g_k + base;
    const float* vp = g_v + base;

    // Stage Q tile (128x64) into Ps region (as float)
#pragma unroll
    for (int i = 0; i < 16; i++) {
        int idx = i * 128 + tid;
        int row = idx >> 4;
        int c4 = (idx & 15) * 4;
        float4 v = *(const float4*)&qp[(size_t)(q0 + row) * DD + c4];
        *(float4*)&Pf[row * PS_STRIDE + c4] = v;
    }
    __syncthreads();

    // Build register-resident Q fragments (scale already folded into g_q)
    uint32_t qf[2][8][4];
#pragma unroll
    for (int mi = 0; mi < 2; mi++)
#pragma unroll
        for (int ks = 0; ks < 8; ks++) {
            int r0 = m0w + mi * 16 + g;
            qf[mi][ks][0] = f2tf(Pf[r0 * PS_STRIDE + tg + 8 * ks]);
            qf[mi][ks][1] = f2tf(Pf[(r0 + 8) * PS_STRIDE + tg + 8 * ks]);
            qf[mi][ks][2] = f2tf(Pf[r0 * PS_STRIDE + tg + 4 + 8 * ks]);
            qf[mi][ks][3] = f2tf(Pf[(r0 + 8) * PS_STRIDE + tg + 4 + 8 * ks]);
        }

    float o[2][8][4];
    float m_[2][2], l_[2][2];
#pragma unroll
    for (int mi = 0; mi < 2; mi++) {
#pragma unroll
        for (int hi = 0; hi < 2; hi++) { m_[mi][hi] = -1e30f; l_[mi][hi] = 0.f; }
#pragma unroll
        for (int nt = 0; nt < 8; nt++)
#pragma unroll
            for (int j = 0; j < 4; j++) o[mi][nt][j] = 0.f;
    }

    const int kt_end = 2 * qt + 1;   // inclusive
    for (int kt = 0; kt <= kt_end; kt++) {
        __syncthreads();   // prev PV reads of Vs/Ps done; q-frag reads done (kt=0)

        // Load K, V tiles (64x64 each), convert to tf32
#pragma unroll
        for (int i = 0; i < 8; i++) {
            int idx = i * 128 + tid;
            int row = idx >> 4;
            int c4 = (idx & 15) * 4;
            float4 kv4 = *(const float4*)&kp[(size_t)(kt * 64 + row) * DD + c4];
            *(uint4*)&Ks[row * KS_STRIDE + c4] =
                make_uint4(f2tf(kv4.x), f2tf(kv4.y), f2tf(kv4.z), f2tf(kv4.w));
            float4 vv4 = *(const float4*)&vp[(size_t)(kt * 64 + row) * DD + c4];
            *(uint4*)&Vs[row * VS_STRIDE + c4] =
                make_uint4(f2tf(vv4.x), f2tf(vv4.y), f2tf(vv4.z), f2tf(vv4.w));
        }
        __syncthreads();

        // S = Q K^T   (per warp: 32x64)
        float s[2][8][4];
#pragma unroll
        for (int mi = 0; mi < 2; mi++)
#pragma unroll
            for (int nt = 0; nt < 8; nt++)
#pragma unroll
                for (int j = 0; j < 4; j++) s[mi][nt][j] = 0.f;

#pragma unroll
        for (int ks = 0; ks < 8; ks++) {
#pragma unroll
            for (int nt = 0; nt < 8; nt++) {
                uint32_t b0 = Ks[(nt * 8 + g) * KS_STRIDE + tg + 8 * ks];
                uint32_t b1 = Ks[(nt * 8 + g) * KS_STRIDE + tg + 4 + 8 * ks];
                mma8(s[0][nt], qf[0][ks], b0, b1);
                mma8(s[1][nt], qf[1][ks], b0, b1);
            }
        }

        // Causal mask (only the last two tiles overlap the diagonal)
        if (kt >= 2 * qt) {
#pragma unroll
            for (int mi = 0; mi < 2; mi++)
#pragma unroll
                for (int nt = 0; nt < 8; nt++)
#pragma unroll
                    for (int j = 0; j < 4; j++) {
                        int row = q0 + m0w + mi * 16 + (j >= 2 ? 8 : 0) + g;
                        int col = kt * 64 + nt * 8 + 2 * tg + (j & 1);
                        if (col > row) s[mi][nt][j] = -1e30f;
                    }
        }

        // Online softmax per row slot; write P (tf32) to smem
#pragma unroll
        for (int mi = 0; mi < 2; mi++)
#pragma unroll
            for (int hi = 0; hi < 2; hi++) {
                float mx = -1e30f;
#pragma unroll
                for (int nt = 0; nt < 8; nt++)
                    mx = fmaxf(mx, fmaxf(s[mi][nt][hi * 2], s[mi][nt][hi * 2 + 1]));
                mx = fmaxf(mx, __shfl_xor_sync(0xffffffffu, mx, 1));
                mx = fmaxf(mx, __shfl_xor_sync(0xffffffffu, mx, 2));
                float mo = m_[mi][hi];
                float mn = fmaxf(mo, mx);
                float fac = __expf(mo - mn);
                float sum = 0.f;
#pragma unroll
                for (int nt = 0; nt < 8; nt++) {
#pragma unroll
                    for (int j2 = 0; j2 < 2; j2++) {
                        float p = __expf(s[mi][nt][hi * 2 + j2] - mn);
                        s[mi][nt][hi * 2 + j2] = p;
                        sum += p;
                    }
                }
                sum += __shfl_xor_sync(0xffffffffu, sum, 1);
                sum += __shfl_xor_sync(0xffffffffu, sum, 2);
                l_[mi][hi] = l_[mi][hi] * fac + sum;
                m_[mi][hi] = mn;
#pragma unroll
                for (int nt = 0; nt < 8; nt++) {
                    o[mi][nt][hi * 2] *= fac;
                    o[mi][nt][hi * 2 + 1] *= fac;
                }
                int r = m0w + mi * 16 + hi * 8 + g;
#pragma unroll
                for (int nt = 0; nt < 8; nt++) {
                    uint2 pu = make_uint2(f2tf(s[mi][nt][hi * 2]),
                                          f2tf(s[mi][nt][hi * 2 + 1]));
                    *(uint2*)&Ps[r * PS_STRIDE + nt * 8 + 2 * tg] = pu;
                }
            }
        __syncthreads();   // P visible to all warps

        // O += P V
#pragma unroll
        for (int ks = 0; ks < 8; ks++) {
            uint32_t pa[2][4];
#pragma unroll
            for (int mi = 0; mi < 2; mi++) {
                int r0 = m0w + mi * 16 + g;
                pa[mi][0] = Ps[r0 * PS_STRIDE + tg + 8 * ks];
                pa[mi][1] = Ps[(r0 + 8) * PS_STRIDE + tg + 8 * ks];
                pa[mi][2] = Ps[r0 * PS_STRIDE + tg + 4 + 8 * ks];
                pa[mi][3] = Ps[(r0 + 8) * PS_STRIDE + tg + 4 + 8 * ks];
            }
#pragma unroll
            for (int nt = 0; nt < 8; nt++) {
                uint32_t b0 = Vs[(8 * ks + tg) * VS_STRIDE + nt * 8 + g];
                uint32_t b1 = Vs[(8 * ks + tg + 4) * VS_STRIDE + nt * 8 + g];
                mma8(o[0][nt], pa[0], b0, b1);
                mma8(o[1][nt], pa[1], b0, b1);
            }
        }
    }

    // Normalize, write to g_y [B,T,E]
#pragma unroll
    for (int mi = 0; mi < 2; mi++)
#pragma unroll
        for (int hi = 0; hi < 2; hi++) {
            float inv = 1.f / l_[mi][hi];
            int t = q0 + m0w + mi * 16 + hi * 8 + g;
#pragma unroll
            for (int nt = 0; nt < 8; nt++) {
                float2 ov = make_float2(o[mi][nt][hi * 2] * inv,
                                        o[mi][nt][hi * 2 + 1] * inv);
                *(float2*)&g_y[((size_t)bb * TT + t) * EE + h * 64 + nt * 8 + 2 * tg] = ov;
            }
        }
}

// ---------------------------------------------------------------------------
// Kernel 3: output projection (tensor core, tf32).
// out[8192,768] = Y[8192,768] @ Wp[768,768] + bp
// ---------------------------------------------------------------------------
__global__ __launch_bounds__(256) void proj_tc_kernel(
    const float* __restrict__ W, const float* __restrict__ bias,
    float* __restrict__ out)
{
    __shared__ uint32_t As[128][36];
    __shared__ uint32_t Bs[32][136];

    const int tid = threadIdx.x;
    const int warp = tid >> 5, lane = tid & 31;
    const int g = lane >> 2, tg = lane & 3;
    const int wm = warp >> 1, wn = warp & 1;
    const int m0 = blockIdx.y * 128, n0 = blockIdx.x * 128;
    const int m0w = wm * 32, n0w = wn * 64;

    float acc[2][8][4];
#pragma unroll
    for (int mi = 0; mi < 2; mi++)
#pragma unroll
        for (int nt = 0; nt < 8; nt++)
#pragma unroll
            for (int j = 0; j < 4; j++) acc[mi][nt][j] = 0.f;

    const int arow = tid >> 1;
    const int acol = (tid & 1) * 16;
    const int brow = tid >> 3;
    const int bcol = (tid & 7) * 16;

    for (int k0 = 0; k0 < EE; k0 += 32) {
#pragma unroll
        for (int j = 0; j < 4; j++) {
            float4 v = *(const float4*)&g_y[(size_t)(m0 + arow) * EE + k0 + acol + j * 4];
            *(uint4*)&As[arow][acol + j * 4] =
                make_uint4(f2tf(v.x), f2tf(v.y), f2tf(v.z), f2tf(v.w));
        }
#pragma unroll
        for (int j = 0; j < 4; j++) {
            float4 v = *(const float4*)&W[(size_t)(k0 + brow) * EE + n0 + bcol + j * 4];
            *(uint4*)&Bs[brow][bcol + j * 4] =
                make_uint4(f2tf(v.x), f2tf(v.y), f2tf(v.z), f2tf(v.w));
        }
        __syncthreads();

#pragma unroll
        for (int ks = 0; ks < 4; ks++) {
            uint32_t af[2][4];
#pragma unroll
            for (int mi = 0; mi < 2; mi++) {
                int r0 = m0w + mi * 16 + g;
                af[mi][0] = As[r0][tg + 8 * ks];
                af[mi][1] = As[r0 + 8][tg + 8 * ks];
                af[mi][2] = As[r0][tg + 4 + 8 * ks];
                af[mi][3] = As[r0 + 8][tg + 4 + 8 * ks];
            }
#pragma unroll
            for (int nt = 0; nt < 8; nt++) {
                uint32_t b0 = Bs[tg + 8 * ks][n0w + nt * 8 + g];
                uint32_t b1 = Bs[tg + 4 + 8 * ks][n0w + nt * 8 + g];
                mma8(acc[0][nt], af[0], b0, b1);
                mma8(acc[1][nt], af[1], b0, b1);
            }
        }
        __syncthreads();
    }

#pragma unroll
    for (int mi = 0; mi < 2; mi++)
#pragma unroll
        for (int hi = 0; hi < 2; hi++) {
            int gm = m0 + m0w + mi * 16 + hi * 8 + g;
#pragma unroll
            for (int nt = 0; nt < 8; nt++) {
                int gn = n0 + n0w + nt * 8 + 2 * tg;
                float2 ov = make_float2(acc[mi][nt][hi * 2] + bias[gn],
                                        acc[mi][nt][hi * 2 + 1] + bias[gn + 1]);
                *(float2*)&out[(size_t)gm * EE + gn] = ov;
            }
        }
}

// ---------------------------------------------------------------------------
extern "C" void kernel_launch(void* const* d_in, const int* in_sizes, int n_in,
                              void* d_out, int out_size)
{
    (void)in_sizes; (void)n_in; (void)out_size;
    const float* x      = (const float*)d_in[0];
    const float* W_attn = (const float*)d_in[1];
    const float* b_attn = (const float*)d_in[2];
    const float* W_proj = (const float*)d_in[3];
    const float* b_proj = (const float*)d_in[4];
    float* out = (float*)d_out;

    // 1) QKV projection -> g_q/g_k/g_v ([B,H,T,D]); q pre-scaled by 0.125
    qkv_tc_kernel<<<dim3(N_QKV / 128, MM / 128), 256>>>(x, W_attn, b_attn);

    // 2) Causal flash attention -> g_y ([B,T,E])
    const int att_smem_bytes = ATT_SMEM_U32 * (int)sizeof(uint32_t);  // 70656
    cudaFuncSetAttribute(attn_tc_kernel,
                         cudaFuncAttributeMaxDynamicSharedMemorySize, att_smem_bytes);
    attn_tc_kernel<<<dim3(TT / 128, HH, BB), 128, att_smem_bytes>>>();

    // 3) Output projection -> d_out
    proj_tc_kernel<<<dim3(EE / 128, MM / 128), 256>>>(W_proj, b_proj, out);
}

// round 4
// speedup vs baseline: 5.9210x; 1.0703x over previous
#include <cuda_runtime.h>
#include <cuda_bf16.h>
#include <cstdint>

// Problem constants
#define BB 2
#define TT 4096
#define EE 768
#define HH 12
#define DD 64
#define MM (BB * TT)        // 8192
#define N_QKV (3 * EE)      // 2304
#define KTOT 768
#define LOG2E 1.4426950408889634f

// Scratch (allocation-free rule: __device__ globals)
__device__ float g_q[(size_t)BB * HH * TT * DD];   // tf32-rounded, scaled 0.125*log2e
__device__ float g_k[(size_t)BB * HH * TT * DD];   // tf32-rounded
__device__ float g_v[(size_t)BB * HH * TT * DD];   // tf32-rounded
__device__ float g_y[(size_t)BB * TT * EE];        // tf32-rounded
__device__ float g_xt[(size_t)MM * EE];            // tf32-rounded X
__device__ float g_wta[(size_t)N_QKV * EE];        // W_attn^T [2304][768], tf32
__device__ float g_wtp[(size_t)EE * EE];           // W_proj^T [768][768], tf32

// ---------------------------------------------------------------------------
// Helpers
// ---------------------------------------------------------------------------
__device__ __forceinline__ uint32_t f2tf(float f) {
    uint32_t r;
    asm("cvt.rna.tf32.f32 %0, %1;" : "=r"(r) : "f"(f));
    return r;
}
__device__ __forceinline__ uint32_t smem_u32(const void* p) {
    uint32_t a;
    asm("{ .reg .u64 t; cvta.to.shared.u64 t, %1; cvt.u32.u64 %0, t; }"
        : "=r"(a) : "l"(p));
    return a;
}
__device__ __forceinline__ void cp16(uint32_t dst, const void* src) {
    asm volatile("cp.async.cg.shared.global [%0], [%1], 16;"
                 :: "r"(dst), "l"(src) : "memory");
}
__device__ __forceinline__ void cp_commit() {
    asm volatile("cp.async.commit_group;" ::: "memory");
}
template<int N> __device__ __forceinline__ void cp_wait() {
    asm volatile("cp.async.wait_group %0;" :: "n"(N) : "memory");
}

// mma.sync m16n8k8 tf32. Fragment layouts (g=lane>>2, tg=lane&3):
//  A: a0(g,tg) a1(g+8,tg) a2(g,tg+4) a3(g+8,tg+4)
//  B: b0(k=tg,n=g) b1(k=tg+4,n=g)
//  C: c0(g,2tg) c1(g,2tg+1) c2(g+8,2tg) c3(g+8,2tg+1)
__device__ __forceinline__ void mma8(float* c, const uint32_t* a,
                                     uint32_t b0, uint32_t b1) {
    asm volatile(
        "mma.sync.aligned.m16n8k8.row.col.f32.tf32.tf32.f32 "
        "{%0,%1,%2,%3}, {%4,%5,%6,%7}, {%8,%9}, {%0,%1,%2,%3};\n"
        : "+f"(c[0]), "+f"(c[1]), "+f"(c[2]), "+f"(c[3])
        : "r"(a[0]), "r"(a[1]), "r"(a[2]), "r"(a[3]), "r"(b0), "r"(b1));
}

extern __shared__ uint32_t dyn_smem[];

// ---------------------------------------------------------------------------
// Prep kernels
// ---------------------------------------------------------------------------
__global__ __launch_bounds__(256) void cvt_x_kernel(const float* __restrict__ src,
                                                    float* __restrict__ dst) {
    size_t i = ((size_t)blockIdx.x * 256 + threadIdx.x) * 4;
    float4 v = *(const float4*)&src[i];
    float4 o;
    o.x = __uint_as_float(f2tf(v.x));
    o.y = __uint_as_float(f2tf(v.y));
    o.z = __uint_as_float(f2tf(v.z));
    o.w = __uint_as_float(f2tf(v.w));
    *(float4*)&dst[i] = o;
}

// dst[n][k] = tf32(src[k][n])
__global__ __launch_bounds__(256) void transpose_cvt_kernel(
    const float* __restrict__ src, float* __restrict__ dst, int K, int N)
{
    __shared__ float t[32][33];
    const int n0 = blockIdx.x * 32, k0 = blockIdx.y * 32;
    const int tx = threadIdx.x & 31, ty = threadIdx.x >> 5;   // 32 x 8
#pragma unroll
    for (int j = 0; j < 4; j++)
        t[ty + j * 8][tx] = src[(size_t)(k0 + ty + j * 8) * N + n0 + tx];
    __syncthreads();
#pragma unroll
    for (int j = 0; j < 4; j++)
        dst[(size_t)(n0 + ty + j * 8) * K + k0 + tx] =
            __uint_as_float(f2tf(t[tx][ty + j * 8]));
}

// ---------------------------------------------------------------------------
// Tensor-core GEMM with cp.async 2-stage pipeline.
// C[m][n] = A[m][k] @ Bt[n][k]^T + bias.  Block 128x128, BK=32, 8 warps,
// warp tile m32 x n64.  Both smem tiles are [row][36] words (4g+tg pattern).
// MODE 0: qkv scatter (rounded, q scaled).  MODE 1: linear fp32 out.
// ---------------------------------------------------------------------------
#define BKT 32
#define NKT (KTOT / BKT)        // 24
#define TILE_W 36
#define ST_WORDS (128 * TILE_W) // 4608 words per tile stage
#define GEMM_SMEM (4 * ST_WORDS * 4)  // 73728 bytes: As0 As1 Bs0 Bs1

template<int MODE>
__global__ __launch_bounds__(256, 2) void gemm_tc_kernel(
    const float* __restrict__ A, const float* __restrict__ Bt,
    const float* __restrict__ bias, float* __restrict__ out)
{
    uint32_t* sm = dyn_smem;
    const uint32_t sb = smem_u32(sm);
    const int tid = threadIdx.x;
    const int warp = tid >> 5, lane = tid & 31;
    const int g = lane >> 2, tg = lane & 3;
    const int wm = warp >> 1, wn = warp & 1;
    const int m0 = blockIdx.y * 128, n0 = blockIdx.x * 128;
    const int m0w = wm * 32, n0w = wn * 64;

    const int lr = tid >> 1;                 // load row 0..127
    const int lc = (tid & 1) * 16;           // word col base 0/16
    const float* asrc0 = A + (size_t)(m0 + lr) * KTOT + lc;
    const float* bsrc0 = Bt + (size_t)(n0 + lr) * KTOT + lc;
    const uint32_t adst0 = sb + (lr * TILE_W + lc) * 4;
    const uint32_t bdst0 = sb + (2 * ST_WORDS + lr * TILE_W + lc) * 4;

    float acc[2][8][4];
#pragma unroll
    for (int mi = 0; mi < 2; mi++)
#pragma unroll
        for (int nt = 0; nt < 8; nt++)
#pragma unroll
            for (int j = 0; j < 4; j++) acc[mi][nt][j] = 0.f;

    auto issue = [&](int i) {
        const int s = i & 1;
        const int k0 = i * BKT;
#pragma unroll
        for (int j = 0; j < 4; j++) {
            cp16(adst0 + (s * ST_WORDS + j * 4) * 4, asrc0 + k0 + j * 4);
            cp16(bdst0 + (s * ST_WORDS + j * 4) * 4, bsrc0 + k0 + j * 4);
        }
        cp_commit();
    };

    issue(0);
    for (int i = 0; i < NKT; i++) {
        const int s = i & 1;
        if (i + 1 < NKT) { issue(i + 1); cp_wait<1>(); }
        else             { cp_wait<0>(); }
        __syncthreads();

        const uint32_t* As = sm + s * ST_WORDS;
        const uint32_t* Bs = sm + (2 + s) * ST_WORDS;
#pragma unroll
        for (int ks = 0; ks < 4; ks++) {
            uint32_t af[2][4];
#pragma unroll
            for (int mi = 0; mi < 2; mi++) {
                int r0 = m0w + mi * 16 + g;
                af[mi][0] = As[r0 * TILE_W + tg + 8 * ks];
                af[mi][1] = As[(r0 + 8) * TILE_W + tg + 8 * ks];
                af[mi][2] = As[r0 * TILE_W + tg + 4 + 8 * ks];
                af[mi][3] = As[(r0 + 8) * TILE_W + tg + 4 + 8 * ks];
            }
#pragma unroll
            for (int nt = 0; nt < 8; nt++) {
                uint32_t b0 = Bs[(n0w + nt * 8 + g) * TILE_W + tg + 8 * ks];
                uint32_t b1 = Bs[(n0w + nt * 8 + g) * TILE_W + tg + 4 + 8 * ks];
                mma8(acc[0][nt], af[0], b0, b1);
                mma8(acc[1][nt], af[1], b0, b1);
            }
        }
        __syncthreads();
    }

    // Epilogue
#pragma unroll
    for (int mi = 0; mi < 2; mi++)
#pragma unroll
        for (int hi = 0; hi < 2; hi++) {
            int gm = m0 + m0w + mi * 16 + hi * 8 + g;
#pragma unroll
            for (int nt = 0; nt < 8; nt++) {
                int gn = n0 + n0w + nt * 8 + 2 * tg;
                float v0 = acc[mi][nt][hi * 2] + bias[gn];
                float v1 = acc[mi][nt][hi * 2 + 1] + bias[gn + 1];
                if (MODE == 0) {
                    int bbv = gm >> 12;
                    int t = gm & (TT - 1);
                    int part = gn / EE;
                    int rem = gn - part * EE;
                    int hh = rem >> 6, d = rem & 63;
                    float* dst = (part == 0) ? g_q : ((part == 1) ? g_k : g_v);
                    float sc = (part == 0) ? (0.125f * LOG2E) : 1.0f;
                    float2 o = make_float2(__uint_as_float(f2tf(v0 * sc)),
                                           __uint_as_float(f2tf(v1 * sc)));
                    *(float2*)&dst[(((size_t)bbv * HH + hh) * TT + t) * DD + d] = o;
                } else {
                    *(float2*)&out[(size_t)gm * EE + gn] = make_float2(v0, v1);
                }
            }
        }
}

// ---------------------------------------------------------------------------
// Causal flash attention (tf32 mma.sync, exp2 softmax, cp.async 2-stage K/V).
// Grid: (T/128, H, B), 128 threads (4 warps). Br=128, Bc=64, D=64.
// smem words: K0[64*68] V0[64*72] K1 V1 P[128*68]
// ---------------------------------------------------------------------------
#define KS_STRIDE 68
#define VS_STRIDE 72
#define PS_STRIDE 68
#define STAGE_W (64 * KS_STRIDE + 64 * VS_STRIDE)   // 8960
#define PS_OFF (2 * STAGE_W)                        // 17920
#define ATT_SMEM ((PS_OFF + 128 * PS_STRIDE) * 4)   // 106496 bytes

__global__ __launch_bounds__(128) void attn_tc_kernel()
{
    uint32_t* sm = dyn_smem;
    const uint32_t sb = smem_u32(sm);
    uint32_t* Ps = sm + PS_OFF;
    float* Pf = (float*)Ps;

    const int tid = threadIdx.x;
    const int warp = tid >> 5, lane = tid & 31;
    const int g = lane >> 2, tg = lane & 3;
    const int qt = blockIdx.x, h = blockIdx.y, bb = blockIdx.z;
    const int q0 = qt * 128;
    const int m0w = warp * 32;

    const size_t base = ((size_t)bb * HH + h) * TT * DD;
    const float* qp = g_q + base;
    const float* kp = g_k + base;
    const float* vp = g_v + base;

    auto issueKV = [&](int kt) {
        const int s = kt & 1;
#pragma unroll
        for (int i = 0; i < 8; i++) {
            int idx = i * 128 + tid;
            int row = idx >> 4;
            int c4 = (idx & 15) * 4;
            cp16(sb + (s * STAGE_W + row * KS_STRIDE + c4) * 4,
                 kp + (size_t)(kt * 64 + row) * DD + c4);
            cp16(sb + (s * STAGE_W + 64 * KS_STRIDE + row * VS_STRIDE + c4) * 4,
                 vp + (size_t)(kt * 64 + row) * DD + c4);
        }
        cp_commit();
    };

    issueKV(0);

    // Stage Q tile (128x64 floats, already tf32-rounded + scaled) into Ps region
#pragma unroll
    for (int i = 0; i < 16; i++) {
        int idx = i * 128 + tid;
        int row = idx >> 4;
        int c4 = (idx & 15) * 4;
        float4 v = *(const float4*)&qp[(size_t)(q0 + row) * DD + c4];
        *(float4*)&Pf[row * PS_STRIDE + c4] = v;
    }
    __syncthreads();

    uint32_t qf[2][8][4];
#pragma unroll
    for (int mi = 0; mi < 2; mi++)
#pragma unroll
        for (int ks = 0; ks < 8; ks++) {
            int r0 = m0w + mi * 16 + g;
            qf[mi][ks][0] = __float_as_uint(Pf[r0 * PS_STRIDE + tg + 8 * ks]);
            qf[mi][ks][1] = __float_as_uint(Pf[(r0 + 8) * PS_STRIDE + tg + 8 * ks]);
            qf[mi][ks][2] = __float_as_uint(Pf[r0 * PS_STRIDE + tg + 4 + 8 * ks]);
            qf[mi][ks][3] = __float_as_uint(Pf[(r0 + 8) * PS_STRIDE + tg + 4 + 8 * ks]);
        }

    float o[2][8][4];
    float m_[2][2], l_[2][2];
#pragma unroll
    for (int mi = 0; mi < 2; mi++) {
#pragma unroll
        for (int hi = 0; hi < 2; hi++) { m_[mi][hi] = -1e30f; l_[mi][hi] = 0.f; }
#pragma unroll
        for (int nt = 0; nt < 8; nt++)
#pragma unroll
            for (int j = 0; j < 4; j++) o[mi][nt][j] = 0.f;
    }

    const int kt_end = 2 * qt + 1;
    for (int kt = 0; kt <= kt_end; kt++) {
        const int s = kt & 1;
        if (kt < kt_end) { issueKV(kt + 1); cp_wait<1>(); }
        else             { cp_wait<0>(); }
        __syncthreads();

        const uint32_t* Ks = sm + s * STAGE_W;
        const uint32_t* Vs = Ks + 64 * KS_STRIDE;

        // S = Q K^T  (scores in log2 units; q pre-scaled by 0.125*log2e)
        float sreg[2][8][4];
#pragma unroll
        for (int mi = 0; mi < 2; mi++)
#pragma unroll
            for (int nt = 0; nt < 8; nt++)
#pragma unroll
                for (int j = 0; j < 4; j++) sreg[mi][nt][j] = 0.f;

#pragma unroll
        for (int ks = 0; ks < 8; ks++) {
#pragma unroll
            for (int nt = 0; nt < 8; nt++) {
                uint32_t b0 = Ks[(nt * 8 + g) * KS_STRIDE + tg + 8 * ks];
                uint32_t b1 = Ks[(nt * 8 + g) * KS_STRIDE + tg + 4 + 8 * ks];
                mma8(sreg[0][nt], qf[0][ks], b0, b1);
                mma8(sreg[1][nt], qf[1][ks], b0, b1);
            }
        }

        if (kt >= 2 * qt) {   // diagonal-overlapping tiles only
#pragma unroll
            for (int mi = 0; mi < 2; mi++)
#pragma unroll
                for (int nt = 0; nt < 8; nt++)
#pragma unroll
                    for (int j = 0; j < 4; j++) {
                        int row = q0 + m0w + mi * 16 + (j >= 2 ? 8 : 0) + g;
                        int col = kt * 64 + nt * 8 + 2 * tg + (j & 1);
                        if (col > row) sreg[mi][nt][j] = -1e30f;
                    }
        }

        // Online softmax (base-2); write P frags (tf32) to smem
#pragma unroll
        for (int mi = 0; mi < 2; mi++)
#pragma unroll
            for (int hi = 0; hi < 2; hi++) {
                float mx = -1e30f;
#pragma unroll
                for (int nt = 0; nt < 8; nt++)
                    mx = fmaxf(mx, fmaxf(sreg[mi][nt][hi * 2], sreg[mi][nt][hi * 2 + 1]));
                mx = fmaxf(mx, __shfl_xor_sync(0xffffffffu, mx, 1));
                mx = fmaxf(mx, __shfl_xor_sync(0xffffffffu, mx, 2));
                float mo = m_[mi][hi];
                float mn = fmaxf(mo, mx);
                float fac = exp2f(mo - mn);
                float sum = 0.f;
#pragma unroll
                for (int nt = 0; nt < 8; nt++) {
#pragma unroll
                    for (int j2 = 0; j2 < 2; j2++) {
                        float p = exp2f(sreg[mi][nt][hi * 2 + j2] - mn);
                        sreg[mi][nt][hi * 2 + j2] = p;
                        sum += p;
                    }
                }
                sum += __shfl_xor_sync(0xffffffffu, sum, 1);
                sum += __shfl_xor_sync(0xffffffffu, sum, 2);
                l_[mi][hi] = l_[mi][hi] * fac + sum;
                m_[mi][hi] = mn;
#pragma unroll
                for (int nt = 0; nt < 8; nt++) {
                    o[mi][nt][hi * 2] *= fac;
                    o[mi][nt][hi * 2 + 1] *= fac;
                }
                int r = m0w + mi * 16 + hi * 8 + g;
#pragma unroll
                for (int nt = 0; nt < 8; nt++) {
                    uint2 pu = make_uint2(f2tf(sreg[mi][nt][hi * 2]),
                                          f2tf(sreg[mi][nt][hi * 2 + 1]));
                    *(uint2*)&Ps[r * PS_STRIDE + nt * 8 + 2 * tg] = pu;
                }
            }
        __syncthreads();

        // O += P V
#pragma unroll
        for (int ks = 0; ks < 8; ks++) {
            uint32_t pa[2][4];
#pragma unroll
            for (int mi = 0; mi < 2; mi++) {
                int r0 = m0w + mi * 16 + g;
                pa[mi][0] = Ps[r0 * PS_STRIDE + tg + 8 * ks];
                pa[mi][1] = Ps[(r0 + 8) * PS_STRIDE + tg + 8 * ks];
                pa[mi][2] = Ps[r0 * PS_STRIDE + tg + 4 + 8 * ks];
                pa[mi][3] = Ps[(r0 + 8) * PS_STRIDE + tg + 4 + 8 * ks];
            }
#pragma unroll
            for (int nt = 0; nt < 8; nt++) {
                uint32_t b0 = Vs[(8 * ks + tg) * VS_STRIDE + nt * 8 + g];
                uint32_t b1 = Vs[(8 * ks + tg + 4) * VS_STRIDE + nt * 8 + g];
                mma8(o[0][nt], pa[0], b0, b1);
                mma8(o[1][nt], pa[1], b0, b1);
            }
        }
        __syncthreads();
    }

    // Normalize, round, write to g_y [B,T,E] (proj consumes it raw)
#pragma unroll
    for (int mi = 0; mi < 2; mi++)
#pragma unroll
        for (int hi = 0; hi < 2; hi++) {
            float inv = 1.f / l_[mi][hi];
            int t = q0 + m0w + mi * 16 + hi * 8 + g;
#pragma unroll
            for (int nt = 0; nt < 8; nt++) {
                float2 ov = make_float2(
                    __uint_as_float(f2tf(o[mi][nt][hi * 2] * inv)),
                    __uint_as_float(f2tf(o[mi][nt][hi * 2 + 1] * inv)));
                *(float2*)&g_y[((size_t)bb * TT + t) * EE + h * 64 + nt * 8 + 2 * tg] = ov;
            }
        }
}

// ---------------------------------------------------------------------------
extern "C" void kernel_launch(void* const* d_in, const int* in_sizes, int n_in,
                              void* d_out, int out_size)
{
    (void)in_sizes; (void)n_in; (void)out_size;
    const float* x      = (const float*)d_in[0];
    const float* W_attn = (const float*)d_in[1];
    const float* b_attn = (const float*)d_in[2];
    const float* W_proj = (const float*)d_in[3];
    const float* b_proj = (const float*)d_in[4];
    float* out = (float*)d_out;

    float *xt, *wta, *wtp, *yv;
    cudaGetSymbolAddress((void**)&xt, g_xt);
    cudaGetSymbolAddress((void**)&wta, g_wta);
    cudaGetSymbolAddress((void**)&wtp, g_wtp);
    cudaGetSymbolAddress((void**)&yv, g_y);

    // 0) Pre-round X; transpose + round weights
    cvt_x_kernel<<<(MM * EE) / (256 * 4), 256>>>(x, xt);
    transpose_cvt_kernel<<<dim3(N_QKV / 32, EE / 32), 256>>>(W_attn, wta, EE, N_QKV);
    transpose_cvt_kernel<<<dim3(EE / 32, EE / 32), 256>>>(W_proj, wtp, EE, EE);

    // 1) QKV projection -> g_q/g_k/g_v (rounded; q scaled by 0.125*log2e)
    cudaFuncSetAttribute(gemm_tc_kernel<0>,
                         cudaFuncAttributeMaxDynamicSharedMemorySize, GEMM_SMEM);
    gemm_tc_kernel<0><<<dim3(N_QKV / 128, MM / 128), 256, GEMM_SMEM>>>(
        xt, wta, b_attn, nullptr);

    // 2) Causal flash attention -> g_y (rounded)
    cudaFuncSetAttribute(attn_tc_kernel,
                         cudaFuncAttributeMaxDynamicSharedMemorySize, ATT_SMEM);
    attn_tc_kernel<<<dim3(TT / 128, HH, BB), 128, ATT_SMEM>>>();

    // 3) Output projection -> d_out (fp32)
    cudaFuncSetAttribute(gemm_tc_kernel<1>,
                         cudaFuncAttributeMaxDynamicSharedMemorySize, GEMM_SMEM);
    gemm_tc_kernel<1><<<dim3(EE / 128, MM / 128), 256, GEMM_SMEM>>>(
        yv, wtp, b_proj, out);
}

// round 6
// speedup vs baseline: 10.8399x; 1.8308x over previous
#include <cuda_runtime.h>
#include <cuda_fp16.h>
#include <cstdint>

// Problem constants
#define BB 2
#define TT 4096
#define EE 768
#define HH 12
#define DD 64
#define MM (BB * TT)        // 8192
#define N_QKV (3 * EE)      // 2304
#define KTOT 768
#define LOG2E 1.4426950408889634f

// Scratch (allocation-free rule: __device__ globals), all fp16
__device__ __half g_q[(size_t)BB * HH * TT * DD];   // [B,H,T,D], scaled 0.125*log2e
__device__ __half g_k[(size_t)BB * HH * TT * DD];   // [B,H,T,D]
__device__ __half g_vt[(size_t)BB * HH * DD * TT];  // [B,H,D,T]  (V transposed)
__device__ __half g_y[(size_t)BB * TT * EE];        // [B,T,E]
__device__ __half g_xt[(size_t)MM * EE];            // X as half
__device__ __half g_wta[(size_t)N_QKV * EE];        // W_attn^T [2304][768]
__device__ __half g_wtp[(size_t)EE * EE];           // W_proj^T [768][768]

// ---------------------------------------------------------------------------
// Helpers
// ---------------------------------------------------------------------------
__device__ __forceinline__ uint32_t smem_u32(const void* p) {
    uint32_t a;
    asm("{ .reg .u64 t; cvta.to.shared.u64 t, %1; cvt.u32.u64 %0, t; }"
        : "=r"(a) : "l"(p));
    return a;
}
__device__ __forceinline__ void cp16(uint32_t dst, const void* src) {
    asm volatile("cp.async.cg.shared.global [%0], [%1], 16;"
                 :: "r"(dst), "l"(src) : "memory");
}
__device__ __forceinline__ void cp_commit() {
    asm volatile("cp.async.commit_group;" ::: "memory");
}
template<int N> __device__ __forceinline__ void cp_wait() {
    asm volatile("cp.async.wait_group %0;" :: "n"(N) : "memory");
}
__device__ __forceinline__ uint32_t packh2(float a, float b) {
    __half2 h = __floats2half2_rn(a, b);     // .x = a (low), .y = b (high)
    return *(uint32_t*)&h;
}

// mma.sync m16n8k16 f16 -> f32.  (g = lane>>2, tg = lane&3)
//  A: a0(row g,  k=2tg..2tg+1) a1(row g+8, same k) a2(row g, k=2tg+8..9) a3(g+8, hi)
//  B: b0(k=2tg..2tg+1, col g)  b1(k=2tg+8..9, col g)
//  C: c0(g,2tg) c1(g,2tg+1) c2(g+8,2tg) c3(g+8,2tg+1)
__device__ __forceinline__ void mma16(float* c, const uint32_t* a,
                                      uint32_t b0, uint32_t b1) {
    asm volatile(
        "mma.sync.aligned.m16n8k16.row.col.f32.f16.f16.f32 "
        "{%0,%1,%2,%3}, {%4,%5,%6,%7}, {%8,%9}, {%0,%1,%2,%3};\n"
        : "+f"(c[0]), "+f"(c[1]), "+f"(c[2]), "+f"(c[3])
        : "r"(a[0]), "r"(a[1]), "r"(a[2]), "r"(a[3]), "r"(b0), "r"(b1));
}

extern __shared__ uint32_t dyn_smem[];

// ---------------------------------------------------------------------------
// Prep kernels
// ---------------------------------------------------------------------------
__global__ __launch_bounds__(256) void cvt_x_kernel(const float* __restrict__ src,
                                                    __half* __restrict__ dst) {
    size_t i = ((size_t)blockIdx.x * 256 + threadIdx.x) * 8;
    float4 v0 = *(const float4*)&src[i];
    float4 v1 = *(const float4*)&src[i + 4];
    uint4 o;
    o.x = packh2(v0.x, v0.y);
    o.y = packh2(v0.z, v0.w);
    o.z = packh2(v1.x, v1.y);
    o.w = packh2(v1.z, v1.w);
    *(uint4*)&dst[i] = o;
}

// dst[n][k] = half(src[k][n])
__global__ __launch_bounds__(256) void transpose_cvt_kernel(
    const float* __restrict__ src, __half* __restrict__ dst, int K, int N)
{
    __shared__ float t[32][33];
    const int n0 = blockIdx.x * 32, k0 = blockIdx.y * 32;
    const int tx = threadIdx.x & 31, ty = threadIdx.x >> 5;   // 32 x 8
#pragma unroll
    for (int j = 0; j < 4; j++)
        t[ty + j * 8][tx] = src[(size_t)(k0 + ty + j * 8) * N + n0 + tx];
    __syncthreads();
#pragma unroll
    for (int j = 0; j < 4; j++)
        dst[(size_t)(n0 + ty + j * 8) * K + k0 + tx] =
            __float2half_rn(t[tx][ty + j * 8]);
}

// ---------------------------------------------------------------------------
// fp16 tensor-core GEMM, cp.async 2-stage.  C = A[m][k] @ Bt[n][k]^T + bias.
// Block 128x128, BK=64 halfs, 8 warps (4m x 2n), warp tile m32 x n64.
// smem rows: 32 data words (64 halfs) padded to 36 words.
// MODE 0: qkv scatter epilogue (q scaled, V transposed).  MODE 1: fp32 out.
// ---------------------------------------------------------------------------
#define BKH 64
#define NKT (KTOT / BKH)        // 12
#define TILE_W 36
#define ST_WORDS (128 * TILE_W) // 4608 words
#define GEMM_SMEM (4 * ST_WORDS * 4)  // 73728 B: A0 A1 B0 B1

template<int MODE>
__global__ __launch_bounds__(256, 2) void gemm_tc_kernel(
    const __half* __restrict__ A, const __half* __restrict__ Bt,
    const float* __restrict__ bias, float* __restrict__ out)
{
    uint32_t* sm = dyn_smem;
    const uint32_t sb = smem_u32(sm);
    const int tid = threadIdx.x;
    const int warp = tid >> 5, lane = tid & 31;
    const int g = lane >> 2, tg = lane & 3;
    const int wm = warp >> 1, wn = warp & 1;
    const int m0 = blockIdx.y * 128, n0 = blockIdx.x * 128;
    const int m0w = wm * 32, n0w = wn * 64;

    const int lr = tid >> 1;                 // load row 0..127
    const int cb = (tid & 1) * 4;            // chunk base (16B chunks)
    const __half* asrc0 = A + (size_t)(m0 + lr) * KTOT + cb * 8;
    const __half* bsrc0 = Bt + (size_t)(n0 + lr) * KTOT + cb * 8;
    const uint32_t adst0 = sb + (lr * TILE_W + cb * 4) * 4;
    const uint32_t bdst0 = sb + (2 * ST_WORDS + lr * TILE_W + cb * 4) * 4;

    float acc[2][8][4];
#pragma unroll
    for (int mi = 0; mi < 2; mi++)
#pragma unroll
        for (int nt = 0; nt < 8; nt++)
#pragma unroll
            for (int j = 0; j < 4; j++) acc[mi][nt][j] = 0.f;

    auto issue = [&](int i) {
        const int s = i & 1;
        const int k0 = i * BKH;
#pragma unroll
        for (int j = 0; j < 4; j++) {
            cp16(adst0 + (s * ST_WORDS + j * 4) * 4, asrc0 + k0 + j * 8);
            cp16(bdst0 + (s * ST_WORDS + j * 4) * 4, bsrc0 + k0 + j * 8);
        }
        cp_commit();
    };

    issue(0);
    for (int i = 0; i < NKT; i++) {
        const int s = i & 1;
        if (i + 1 < NKT) { issue(i + 1); cp_wait<1>(); }
        else             { cp_wait<0>(); }
        __syncthreads();

        const uint32_t* As = sm + s * ST_WORDS;
        const uint32_t* Bs = sm + (2 + s) * ST_WORDS;
#pragma unroll
        for (int ks = 0; ks < 4; ks++) {
            uint32_t af[2][4];
#pragma unroll
            for (int mi = 0; mi < 2; mi++) {
                int r0 = m0w + mi * 16 + g;
                af[mi][0] = As[r0 * TILE_W + tg + 8 * ks];
                af[mi][1] = As[(r0 + 8) * TILE_W + tg + 8 * ks];
                af[mi][2] = As[r0 * TILE_W + tg + 4 + 8 * ks];
                af[mi][3] = As[(r0 + 8) * TILE_W + tg + 4 + 8 * ks];
            }
#pragma unroll
            for (int nt = 0; nt < 8; nt++) {
                uint32_t b0 = Bs[(n0w + nt * 8 + g) * TILE_W + tg + 8 * ks];
                uint32_t b1 = Bs[(n0w + nt * 8 + g) * TILE_W + tg + 4 + 8 * ks];
                mma16(acc[0][nt], af[0], b0, b1);
                mma16(acc[1][nt], af[1], b0, b1);
            }
        }
        __syncthreads();
    }

    // Epilogue
#pragma unroll
    for (int mi = 0; mi < 2; mi++)
#pragma unroll
        for (int hi = 0; hi < 2; hi++) {
            int gm = m0 + m0w + mi * 16 + hi * 8 + g;
#pragma unroll
            for (int nt = 0; nt < 8; nt++) {
                int gn = n0 + n0w + nt * 8 + 2 * tg;
                float v0 = acc[mi][nt][hi * 2] + bias[gn];
                float v1 = acc[mi][nt][hi * 2 + 1] + bias[gn + 1];
                if (MODE == 0) {
                    int bbv = gm >> 12;
                    int t = gm & (TT - 1);
                    int part = gn / EE;
                    int rem = gn - part * EE;
                    int hh = rem >> 6, d = rem & 63;
                    if (part == 0) {
                        __half2 h = __floats2half2_rn(v0 * (0.125f * LOG2E),
                                                      v1 * (0.125f * LOG2E));
                        *(__half2*)&g_q[(((size_t)bbv * HH + hh) * TT + t) * DD + d] = h;
                    } else if (part == 1) {
                        __half2 h = __floats2half2_rn(v0, v1);
                        *(__half2*)&g_k[(((size_t)bbv * HH + hh) * TT + t) * DD + d] = h;
                    } else {
                        size_t vb = ((size_t)bbv * HH + hh) * DD;
                        g_vt[(vb + d) * TT + t] = __float2half_rn(v0);
                        g_vt[(vb + d + 1) * TT + t] = __float2half_rn(v1);
                    }
                } else {
                    *(float2*)&out[(size_t)gm * EE + gn] = make_float2(v0, v1);
                }
            }
        }
}

// ---------------------------------------------------------------------------
// Causal flash attention, fp16 mma, exp2 softmax, P kept in registers.
// Grid: (T/128, H, B), 256 threads (8 warps), warp tile m16 x kv64.
// 3-stage cp.async K/V ring, one __syncthreads per kv tile.
// smem words: Q[128*36] + 3 stages of (K[64*36] + V[64*36]).
// ---------------------------------------------------------------------------
#define AT_W 36
#define QS_WORDS (128 * AT_W)       // 4608
#define KV_WORDS (64 * AT_W)        // 2304
#define STAGE_W (2 * KV_WORDS)      // 4608
#define ATT_SMEM ((QS_WORDS + 3 * STAGE_W) * 4)   // 73728 B

__global__ __launch_bounds__(256, 2) void attn_tc_kernel()
{
    uint32_t* sm = dyn_smem;
    const uint32_t sb = smem_u32(sm);

    const int tid = threadIdx.x;
    const int warp = tid >> 5, lane = tid & 31;
    const int g = lane >> 2, tg = lane & 3;
    const int qt = blockIdx.x, h = blockIdx.y, bb = blockIdx.z;
    const int q0 = qt * 128;

    const size_t hb = (size_t)bb * HH + h;
    const __half* qp = g_q + hb * TT * DD;
    const __half* kp = g_k + hb * TT * DD;
    const __half* vtp = g_vt + hb * DD * TT;

    // Issue Q tile (128 rows x 64 halfs) -> Qs
#pragma unroll
    for (int i = 0; i < 4; i++) {
        int idx = i * 256 + tid;
        int row = idx >> 3, c = idx & 7;
        cp16(sb + (row * AT_W + c * 4) * 4, qp + (size_t)(q0 + row) * DD + c * 8);
    }
    cp_commit();

    auto issueKV = [&](int kt) {
        const int st = kt % 3;
        const uint32_t base = sb + (QS_WORDS + st * STAGE_W) * 4;
#pragma unroll
        for (int i = 0; i < 4; i++) {
            int idx = i * 256 + tid;
            if (idx < 512) {                    // K rows (kv)
                int row = idx >> 3, c = idx & 7;
                cp16(base + (row * AT_W + c * 4) * 4,
                     kp + (size_t)(kt * 64 + row) * DD + c * 8);
            } else {                            // V^T rows (d)
                int j = idx - 512;
                int d = j >> 3, c = j & 7;
                cp16(base + (KV_WORDS + d * AT_W + c * 4) * 4,
                     vtp + (size_t)d * TT + kt * 64 + c * 8);
            }
        }
        cp_commit();
    };

    const int kt_end = 2 * qt + 1;   // inclusive
    issueKV(0);
    if (kt_end >= 1) issueKV(1);

    // Wait for Q (it is the oldest group), build Q fragments
    if (kt_end >= 1) cp_wait<2>(); else cp_wait<1>();
    __syncthreads();

    uint32_t qf[4][4];
    {
        const uint32_t* Qs = sm;
        int r0 = warp * 16 + g;
#pragma unroll
        for (int c = 0; c < 4; c++) {
            qf[c][0] = Qs[r0 * AT_W + tg + 8 * c];
            qf[c][1] = Qs[(r0 + 8) * AT_W + tg + 8 * c];
            qf[c][2] = Qs[r0 * AT_W + tg + 4 + 8 * c];
            qf[c][3] = Qs[(r0 + 8) * AT_W + tg + 4 + 8 * c];
        }
    }

    float o[8][4];
    float m0_ = -1e30f, m1_ = -1e30f, l0_ = 0.f, l1_ = 0.f;
#pragma unroll
    for (int nt = 0; nt < 8; nt++)
#pragma unroll
        for (int j = 0; j < 4; j++) o[nt][j] = 0.f;

    for (int kt = 0; kt <= kt_end; kt++) {
        // Stage kt%3 ready when group KV(kt) retired; pending <= KV(kt+1)
        if (kt + 1 <= kt_end) cp_wait<1>(); else cp_wait<0>();
        __syncthreads();

        const uint32_t* Ks = sm + QS_WORDS + (kt % 3) * STAGE_W;
        const uint32_t* Vs = Ks + KV_WORDS;

        // S = Q K^T  (16 x 64 per warp), log2-domain scores
        float s[8][4];
#pragma unroll
        for (int nt = 0; nt < 8; nt++)
#pragma unroll
            for (int j = 0; j < 4; j++) s[nt][j] = 0.f;
#pragma unroll
        for (int c = 0; c < 4; c++)
#pragma unroll
            for (int nt = 0; nt < 8; nt++) {
                uint32_t b0 = Ks[(nt * 8 + g) * AT_W + tg + 8 * c];
                uint32_t b1 = Ks[(nt * 8 + g) * AT_W + tg + 4 + 8 * c];
                mma16(s[nt], qf[c], b0, b1);
            }

        // Causal mask (diagonal-overlapping tiles only)
        if (kt >= 2 * qt) {
            int row0 = q0 + warp * 16 + g;
#pragma unroll
            for (int nt = 0; nt < 8; nt++) {
                int col = kt * 64 + nt * 8 + 2 * tg;
                if (col > row0)     s[nt][0] = -1e30f;
                if (col + 1 > row0) s[nt][1] = -1e30f;
                if (col > row0 + 8)     s[nt][2] = -1e30f;
                if (col + 1 > row0 + 8) s[nt][3] = -1e30f;
            }
        }

        // Online softmax (base-2) for rows g and g+8
        float mx0 = -1e30f, mx1 = -1e30f;
#pragma unroll
        for (int nt = 0; nt < 8; nt++) {
            mx0 = fmaxf(mx0, fmaxf(s[nt][0], s[nt][1]));
            mx1 = fmaxf(mx1, fmaxf(s[nt][2], s[nt][3]));
        }
        mx0 = fmaxf(mx0, __shfl_xor_sync(0xffffffffu, mx0, 1));
        mx0 = fmaxf(mx0, __shfl_xor_sync(0xffffffffu, mx0, 2));
        mx1 = fmaxf(mx1, __shfl_xor_sync(0xffffffffu, mx1, 1));
        mx1 = fmaxf(mx1, __shfl_xor_sync(0xffffffffu, mx1, 2));
        float mn0 = fmaxf(m0_, mx0), mn1 = fmaxf(m1_, mx1);
        float f0 = exp2f(m0_ - mn0), f1 = exp2f(m1_ - mn1);
        float sum0 = 0.f, sum1 = 0.f;
#pragma unroll
        for (int nt = 0; nt < 8; nt++) {
            float p0 = exp2f(s[nt][0] - mn0);
            float p1 = exp2f(s[nt][1] - mn0);
            float p2 = exp2f(s[nt][2] - mn1);
            float p3 = exp2f(s[nt][3] - mn1);
            sum0 += p0 + p1; sum1 += p2 + p3;
            s[nt][0] = p0; s[nt][1] = p1; s[nt][2] = p2; s[nt][3] = p3;
        }
        sum0 += __shfl_xor_sync(0xffffffffu, sum0, 1);
        sum0 += __shfl_xor_sync(0xffffffffu, sum0, 2);
        sum1 += __shfl_xor_sync(0xffffffffu, sum1, 1);
        sum1 += __shfl_xor_sync(0xffffffffu, sum1, 2);
        l0_ = l0_ * f0 + sum0; l1_ = l1_ * f1 + sum1;
        m0_ = mn0; m1_ = mn1;
#pragma unroll
        for (int nt = 0; nt < 8; nt++) {
            o[nt][0] *= f0; o[nt][1] *= f0;
            o[nt][2] *= f1; o[nt][3] *= f1;
        }

        // O += P V : repack S fragments (C layout) into A fragments in-register
#pragma unroll
        for (int c = 0; c < 4; c++) {
            uint32_t pa[4];
            pa[0] = packh2(s[2 * c][0], s[2 * c][1]);
            pa[1] = packh2(s[2 * c][2], s[2 * c][3]);
            pa[2] = packh2(s[2 * c + 1][0], s[2 * c + 1][1]);
            pa[3] = packh2(s[2 * c + 1][2], s[2 * c + 1][3]);
#pragma unroll
            for (int nt = 0; nt < 8; nt++) {
                uint32_t b0 = Vs[(nt * 8 + g) * AT_W + tg + 8 * c];
                uint32_t b1 = Vs[(nt * 8 + g) * AT_W + tg + 4 + 8 * c];
                mma16(o[nt], pa, b0, b1);
            }
        }

        __syncthreads();   // all reads of this stage done before ring reuse
        if (kt + 2 <= kt_end) issueKV(kt + 2);
    }

    // Normalize, convert, write g_y [B,T,E]
    float inv0 = 1.f / l0_, inv1 = 1.f / l1_;
    int t0 = q0 + warp * 16 + g;
#pragma unroll
    for (int nt = 0; nt < 8; nt++) {
        int col = h * 64 + nt * 8 + 2 * tg;
        *(__half2*)&g_y[((size_t)bb * TT + t0) * EE + col] =
            __floats2half2_rn(o[nt][0] * inv0, o[nt][1] * inv0);
        *(__half2*)&g_y[((size_t)bb * TT + t0 + 8) * EE + col] =
            __floats2half2_rn(o[nt][2] * inv1, o[nt][3] * inv1);
    }
}

// ---------------------------------------------------------------------------
extern "C" void kernel_launch(void* const* d_in, const int* in_sizes, int n_in,
                              void* d_out, int out_size)
{
    (void)in_sizes; (void)n_in; (void)out_size;
    const float* x      = (const float*)d_in[0];
    const float* W_attn = (const float*)d_in[1];
    const float* b_attn = (const float*)d_in[2];
    const float* W_proj = (const float*)d_in[3];
    const float* b_proj = (const float*)d_in[4];
    float* out = (float*)d_out;

    __half *xt, *wta, *wtp, *yv;
    cudaGetSymbolAddress((void**)&xt, g_xt);
    cudaGetSymbolAddress((void**)&wta, g_wta);
    cudaGetSymbolAddress((void**)&wtp, g_wtp);
    cudaGetSymbolAddress((void**)&yv, g_y);

    // 0) Convert X to half; transpose + convert weights
    cvt_x_kernel<<<(MM * EE) / (256 * 8), 256>>>(x, xt);
    transpose_cvt_kernel<<<dim3(N_QKV / 32, EE / 32), 256>>>(W_attn, wta, EE, N_QKV);
    transpose_cvt_kernel<<<dim3(EE / 32, EE / 32), 256>>>(W_proj, wtp, EE, EE);

    // 1) QKV projection -> g_q/g_k/g_vt (q scaled by 0.125*log2e; V transposed)
    cudaFuncSetAttribute(gemm_tc_kernel<0>,
                         cudaFuncAttributeMaxDynamicSharedMemorySize, GEMM_SMEM);
    gemm_tc_kernel<0><<<dim3(N_QKV / 128, MM / 128), 256, GEMM_SMEM>>>(
        xt, wta, b_attn, nullptr);

    // 2) Causal flash attention -> g_y
    cudaFuncSetAttribute(attn_tc_kernel,
                         cudaFuncAttributeMaxDynamicSharedMemorySize, ATT_SMEM);
    attn_tc_kernel<<<dim3(TT / 128, HH, BB), 256, ATT_SMEM>>>();

    // 3) Output projection -> d_out (fp32)
    cudaFuncSetAttribute(gemm_tc_kernel<1>,
                         cudaFuncAttributeMaxDynamicSharedMemorySize, GEMM_SMEM);
    gemm_tc_kernel<1><<<dim3(EE / 128, MM / 128), 256, GEMM_SMEM>>>(
        yv, wtp, b_proj, out);
}

// round 7
// speedup vs baseline: 11.5424x; 1.0648x over previous
#include <cuda_runtime.h>
#include <cuda_fp16.h>
#include <cstdint>

// Problem constants
#define BB 2
#define TT 4096
#define EE 768
#define HH 12
#define DD 64
#define MM (BB * TT)        // 8192
#define N_QKV (3 * EE)      // 2304
#define KTOT 768
#define LOG2E 1.4426950408889634f

// Scratch (allocation-free rule: __device__ globals), all fp16
__device__ __half g_q[(size_t)BB * HH * TT * DD];   // [B,H,T,D], scaled 0.125*log2e
__device__ __half g_k[(size_t)BB * HH * TT * DD];   // [B,H,T,D]
__device__ __half g_vt[(size_t)BB * HH * DD * TT];  // [B,H,D,T]  (V transposed)
__device__ __half g_y[(size_t)BB * TT * EE];        // [B,T,E]
__device__ __half g_xt[(size_t)MM * EE];            // X as half
__device__ __half g_wta[(size_t)N_QKV * EE];        // W_attn^T [2304][768]
__device__ __half g_wtp[(size_t)EE * EE];           // W_proj^T [768][768]

// ---------------------------------------------------------------------------
// Helpers
// ---------------------------------------------------------------------------
__device__ __forceinline__ uint32_t smem_u32(const void* p) {
    uint32_t a;
    asm("{ .reg .u64 t; cvta.to.shared.u64 t, %1; cvt.u32.u64 %0, t; }"
        : "=r"(a) : "l"(p));
    return a;
}
__device__ __forceinline__ void cp16(uint32_t dst, const void* src) {
    asm volatile("cp.async.cg.shared.global [%0], [%1], 16;"
                 :: "r"(dst), "l"(src) : "memory");
}
__device__ __forceinline__ void cp_commit() {
    asm volatile("cp.async.commit_group;" ::: "memory");
}
template<int N> __device__ __forceinline__ void cp_wait() {
    asm volatile("cp.async.wait_group %0;" :: "n"(N) : "memory");
}
__device__ __forceinline__ uint32_t packh2(float a, float b) {
    __half2 h = __floats2half2_rn(a, b);
    return *(uint32_t*)&h;
}
// ldmatrix x4: four 8x8 b16 matrices; lane l supplies the row address for
// matrix l/8, row l%8. Result reg i = matrix i, lane mapping (row l/4, col 2(l%4)).
__device__ __forceinline__ void ldsm4(uint32_t* r, uint32_t addr) {
    asm volatile("ldmatrix.sync.aligned.m8n8.x4.shared.b16 {%0,%1,%2,%3}, [%4];"
                 : "=r"(r[0]), "=r"(r[1]), "=r"(r[2]), "=r"(r[3]) : "r"(addr));
}

// mma.sync m16n8k16 f16 -> f32.
__device__ __forceinline__ void mma16(float* c, const uint32_t* a,
                                      uint32_t b0, uint32_t b1) {
    asm volatile(
        "mma.sync.aligned.m16n8k16.row.col.f32.f16.f16.f32 "
        "{%0,%1,%2,%3}, {%4,%5,%6,%7}, {%8,%9}, {%0,%1,%2,%3};\n"
        : "+f"(c[0]), "+f"(c[1]), "+f"(c[2]), "+f"(c[3])
        : "r"(a[0]), "r"(a[1]), "r"(a[2]), "r"(a[3]), "r"(b0), "r"(b1));
}

extern __shared__ uint32_t dyn_smem[];

// ---------------------------------------------------------------------------
// Prep kernels
// ---------------------------------------------------------------------------
__global__ __launch_bounds__(256) void cvt_x_kernel(const float* __restrict__ src,
                                                    __half* __restrict__ dst) {
    size_t i = ((size_t)blockIdx.x * 256 + threadIdx.x) * 8;
    float4 v0 = *(const float4*)&src[i];
    float4 v1 = *(const float4*)&src[i + 4];
    uint4 o;
    o.x = packh2(v0.x, v0.y);
    o.y = packh2(v0.z, v0.w);
    o.z = packh2(v1.x, v1.y);
    o.w = packh2(v1.z, v1.w);
    *(uint4*)&dst[i] = o;
}

// dst[n][k] = half(src[k][n])
__global__ __launch_bounds__(256) void transpose_cvt_kernel(
    const float* __restrict__ src, __half* __restrict__ dst, int K, int N)
{
    __shared__ float t[32][33];
    const int n0 = blockIdx.x * 32, k0 = blockIdx.y * 32;
    const int tx = threadIdx.x & 31, ty = threadIdx.x >> 5;   // 32 x 8
#pragma unroll
    for (int j = 0; j < 4; j++)
        t[ty + j * 8][tx] = src[(size_t)(k0 + ty + j * 8) * N + n0 + tx];
    __syncthreads();
#pragma unroll
    for (int j = 0; j < 4; j++)
        dst[(size_t)(n0 + ty + j * 8) * K + k0 + tx] =
            __float2half_rn(t[tx][ty + j * 8]);
}

// ---------------------------------------------------------------------------
// fp16 tensor-core GEMM, cp.async 2-stage, LDSM fragment loads.
// C = A[m][k] @ Bt[n][k]^T + bias.  Block 128x128, BK=64 halfs, 8 warps
// (4m x 2n), warp tile m32 x n64.  smem rows padded to 36 words (144 B).
// MODE 0: qkv scatter epilogue (q scaled, V transposed).  MODE 1: fp32 out.
// ---------------------------------------------------------------------------
#define BKH 64
#define NKT (KTOT / BKH)        // 12
#define TILE_W 36
#define ST_WORDS (128 * TILE_W) // 4608 words
#define GEMM_SMEM (4 * ST_WORDS * 4)  // 73728 B: A0 A1 B0 B1

template<int MODE>
__global__ __launch_bounds__(256, 2) void gemm_tc_kernel(
    const __half* __restrict__ A, const __half* __restrict__ Bt,
    const float* __restrict__ bias, float* __restrict__ out)
{
    uint32_t* sm = dyn_smem;
    const uint32_t sb = smem_u32(sm);
    const int tid = threadIdx.x;
    const int warp = tid >> 5, lane = tid & 31;
    const int g = lane >> 2, tg = lane & 3;
    const int wm = warp >> 1, wn = warp & 1;
    const int m0 = blockIdx.y * 128, n0 = blockIdx.x * 128;
    const int m0w = wm * 32, n0w = wn * 64;

    // cp.async staging
    const int lr = tid >> 1;                 // load row 0..127
    const int cb = (tid & 1) * 4;            // chunk base (16B chunks)
    const __half* asrc0 = A + (size_t)(m0 + lr) * KTOT + cb * 8;
    const __half* bsrc0 = Bt + (size_t)(n0 + lr) * KTOT + cb * 8;
    const uint32_t adst0 = sb + (lr * TILE_W + cb * 4) * 4;
    const uint32_t bdst0 = sb + (2 * ST_WORDS + lr * TILE_W + cb * 4) * 4;

    // LDSM per-lane base addresses.
    // A frags (mi tile): mats a0(m0-7,k0-7) a1(m8-15,k0-7) a2(m0-7,k8-15) a3(m8-15,k8-15)
    const int mt = lane >> 3, mr = lane & 7;
    uint32_t aoff[2];
#pragma unroll
    for (int mi = 0; mi < 2; mi++)
        aoff[mi] = sb + ((m0w + mi * 16 + (mt & 1) * 8 + mr) * TILE_W + (mt >> 1) * 4) * 4;
    // B frags (np tile = n16): mats b0(n0-7,k0-7) b1(n0-7,k8-15) b0'(n8-15,k0-7) b1'(n8-15,k8-15)
    uint32_t boff[4];
#pragma unroll
    for (int np = 0; np < 4; np++)
        boff[np] = sb + (2 * ST_WORDS + (n0w + np * 16 + (mt >> 1) * 8 + mr) * TILE_W
                         + (mt & 1) * 4) * 4;

    float acc[2][8][4];
#pragma unroll
    for (int mi = 0; mi < 2; mi++)
#pragma unroll
        for (int nt = 0; nt < 8; nt++)
#pragma unroll
            for (int j = 0; j < 4; j++) acc[mi][nt][j] = 0.f;

    auto issue = [&](int i) {
        const int s = i & 1;
        const int k0 = i * BKH;
#pragma unroll
        for (int j = 0; j < 4; j++) {
            cp16(adst0 + (s * ST_WORDS + j * 4) * 4, asrc0 + k0 + j * 8);
            cp16(bdst0 + (s * ST_WORDS + j * 4) * 4, bsrc0 + k0 + j * 8);
        }
        cp_commit();
    };

    issue(0);
    for (int i = 0; i < NKT; i++) {
        const int s = i & 1;
        if (i + 1 < NKT) { issue(i + 1); cp_wait<1>(); }
        else             { cp_wait<0>(); }
        __syncthreads();

        const uint32_t soff = (uint32_t)(s * ST_WORDS * 4);
#pragma unroll
        for (int ks = 0; ks < 4; ks++) {
            const uint32_t ko = soff + ks * 32;        // 16 halfs = 32 B per ks
            uint32_t af[2][4], bf[4][4];
            ldsm4(af[0], aoff[0] + ko);
            ldsm4(af[1], aoff[1] + ko);
#pragma unroll
            for (int np = 0; np < 4; np++) ldsm4(bf[np], boff[np] + ko);
#pragma unroll
            for (int np = 0; np < 4; np++) {
                mma16(acc[0][2 * np],     af[0], bf[np][0], bf[np][1]);
                mma16(acc[0][2 * np + 1], af[0], bf[np][2], bf[np][3]);
                mma16(acc[1][2 * np],     af[1], bf[np][0], bf[np][1]);
                mma16(acc[1][2 * np + 1], af[1], bf[np][2], bf[np][3]);
            }
        }
        __syncthreads();
    }

    // Epilogue
#pragma unroll
    for (int mi = 0; mi < 2; mi++)
#pragma unroll
        for (int hi = 0; hi < 2; hi++) {
            int gm = m0 + m0w + mi * 16 + hi * 8 + g;
#pragma unroll
            for (int nt = 0; nt < 8; nt++) {
                int gn = n0 + n0w + nt * 8 + 2 * tg;
                float v0 = acc[mi][nt][hi * 2] + bias[gn];
                float v1 = acc[mi][nt][hi * 2 + 1] + bias[gn + 1];
                if (MODE == 0) {
                    int bbv = gm >> 12;
                    int t = gm & (TT - 1);
                    int part = gn / EE;
                    int rem = gn - part * EE;
                    int hh = rem >> 6, d = rem & 63;
                    if (part == 0) {
                        __half2 h = __floats2half2_rn(v0 * (0.125f * LOG2E),
                                                      v1 * (0.125f * LOG2E));
                        *(__half2*)&g_q[(((size_t)bbv * HH + hh) * TT + t) * DD + d] = h;
                    } else if (part == 1) {
                        __half2 h = __floats2half2_rn(v0, v1);
                        *(__half2*)&g_k[(((size_t)bbv * HH + hh) * TT + t) * DD + d] = h;
                    } else {
                        size_t vb = ((size_t)bbv * HH + hh) * DD;
                        g_vt[(vb + d) * TT + t] = __float2half_rn(v0);
                        g_vt[(vb + d + 1) * TT + t] = __float2half_rn(v1);
                    }
                } else {
                    *(float2*)&out[(size_t)gm * EE + gn] = make_float2(v0, v1);
                }
            }
        }
}

// ---------------------------------------------------------------------------
// Causal flash attention, fp16 mma + LDSM, exp2 softmax, P in registers.
// Grid: (T/128, H, B), 256 threads (8 warps), warp tile m16 x kv64.
// 3-stage cp.async K/V ring, one __syncthreads per kv tile.
// smem words: Q[128*36] + 3 stages of (K[64*36] + V[64*36]).
// ---------------------------------------------------------------------------
#define AT_W 36
#define QS_WORDS (128 * AT_W)       // 4608
#define KV_WORDS (64 * AT_W)        // 2304
#define STAGE_W (2 * KV_WORDS)      // 4608
#define ATT_SMEM ((QS_WORDS + 3 * STAGE_W) * 4)   // 73728 B

__global__ __launch_bounds__(256, 2) void attn_tc_kernel()
{
    uint32_t* sm = dyn_smem;
    const uint32_t sb = smem_u32(sm);

    const int tid = threadIdx.x;
    const int warp = tid >> 5, lane = tid & 31;
    const int g = lane >> 2, tg = lane & 3;
    const int qt = blockIdx.x, h = blockIdx.y, bb = blockIdx.z;
    const int q0 = qt * 128;

    const size_t hb = (size_t)bb * HH + h;
    const __half* qp = g_q + hb * TT * DD;
    const __half* kp = g_k + hb * TT * DD;
    const __half* vtp = g_vt + hb * DD * TT;

    // Issue Q tile (128 rows x 64 halfs) -> Qs
#pragma unroll
    for (int i = 0; i < 4; i++) {
        int idx = i * 256 + tid;
        int row = idx >> 3, c = idx & 7;
        cp16(sb + (row * AT_W + c * 4) * 4, qp + (size_t)(q0 + row) * DD + c * 8);
    }
    cp_commit();

    auto issueKV = [&](int kt) {
        const int st = kt % 3;
        const uint32_t base = sb + (QS_WORDS + st * STAGE_W) * 4;
#pragma unroll
        for (int i = 0; i < 4; i++) {
            int idx = i * 256 + tid;
            if (idx < 512) {                    // K rows (kv)
                int row = idx >> 3, c = idx & 7;
                cp16(base + (row * AT_W + c * 4) * 4,
                     kp + (size_t)(kt * 64 + row) * DD + c * 8);
            } else {                            // V^T rows (d)
                int j = idx - 512;
                int d = j >> 3, c = j & 7;
                cp16(base + (KV_WORDS + d * AT_W + c * 4) * 4,
                     vtp + (size_t)d * TT + kt * 64 + c * 8);
            }
        }
        cp_commit();
    };

    const int kt_end = 2 * qt + 1;   // inclusive
    issueKV(0);
    if (kt_end >= 1) issueKV(1);

    // Wait for Q, build Q fragments with LDSM
    if (kt_end >= 1) cp_wait<2>(); else cp_wait<1>();
    __syncthreads();

    const int mt = lane >> 3, mr = lane & 7;
    uint32_t qf[4][4];
    {
        const uint32_t qrow = sb + ((warp * 16 + (mt & 1) * 8 + mr) * AT_W) * 4;
#pragma unroll
        for (int c = 0; c < 4; c++)
            ldsm4(qf[c], qrow + (c * 8 + (mt >> 1) * 4) * 4);
    }
    // B-frag per-lane base offsets (within a K or V tile region)
    uint32_t bofs[4];
#pragma unroll
    for (int np = 0; np < 4; np++)
        bofs[np] = ((np * 16 + (mt >> 1) * 8 + mr) * AT_W + (mt & 1) * 4) * 4;

    float o[8][4];
    float m0_ = -1e30f, m1_ = -1e30f, l0_ = 0.f, l1_ = 0.f;
#pragma unroll
    for (int nt = 0; nt < 8; nt++)
#pragma unroll
        for (int j = 0; j < 4; j++) o[nt][j] = 0.f;

    for (int kt = 0; kt <= kt_end; kt++) {
        if (kt + 1 <= kt_end) cp_wait<1>(); else cp_wait<0>();
        __syncthreads();

        const uint32_t kbase = sb + (QS_WORDS + (kt % 3) * STAGE_W) * 4;
        const uint32_t vbase = kbase + KV_WORDS * 4;

        // S = Q K^T  (16 x 64 per warp), log2-domain scores
        float s[8][4];
#pragma unroll
        for (int nt = 0; nt < 8; nt++)
#pragma unroll
            for (int j = 0; j < 4; j++) s[nt][j] = 0.f;
#pragma unroll
        for (int c = 0; c < 4; c++) {
            uint32_t bf[4][4];
#pragma unroll
            for (int np = 0; np < 4; np++) ldsm4(bf[np], kbase + bofs[np] + c * 32);
#pragma unroll
            for (int np = 0; np < 4; np++) {
                mma16(s[2 * np],     qf[c], bf[np][0], bf[np][1]);
                mma16(s[2 * np + 1], qf[c], bf[np][2], bf[np][3]);
            }
        }

        // Causal mask (diagonal-overlapping tiles only)
        if (kt >= 2 * qt) {
            int row0 = q0 + warp * 16 + g;
#pragma unroll
            for (int nt = 0; nt < 8; nt++) {
                int col = kt * 64 + nt * 8 + 2 * tg;
                if (col > row0)     s[nt][0] = -1e30f;
                if (col + 1 > row0) s[nt][1] = -1e30f;
                if (col > row0 + 8)     s[nt][2] = -1e30f;
                if (col + 1 > row0 + 8) s[nt][3] = -1e30f;
            }
        }

        // Online softmax (base-2) for rows g and g+8
        float mx0 = -1e30f, mx1 = -1e30f;
#pragma unroll
        for (int nt = 0; nt < 8; nt++) {
            mx0 = fmaxf(mx0, fmaxf(s[nt][0], s[nt][1]));
            mx1 = fmaxf(mx1, fmaxf(s[nt][2], s[nt][3]));
        }
        mx0 = fmaxf(mx0, __shfl_xor_sync(0xffffffffu, mx0, 1));
        mx0 = fmaxf(mx0, __shfl_xor_sync(0xffffffffu, mx0, 2));
        mx1 = fmaxf(mx1, __shfl_xor_sync(0xffffffffu, mx1, 1));
        mx1 = fmaxf(mx1, __shfl_xor_sync(0xffffffffu, mx1, 2));
        float mn0 = fmaxf(m0_, mx0), mn1 = fmaxf(m1_, mx1);
        float f0 = exp2f(m0_ - mn0), f1 = exp2f(m1_ - mn1);
        float sum0 = 0.f, sum1 = 0.f;
#pragma unroll
        for (int nt = 0; nt < 8; nt++) {
            float p0 = exp2f(s[nt][0] - mn0);
            float p1 = exp2f(s[nt][1] - mn0);
            float p2 = exp2f(s[nt][2] - mn1);
            float p3 = exp2f(s[nt][3] - mn1);
            sum0 += p0 + p1; sum1 += p2 + p3;
            s[nt][0] = p0; s[nt][1] = p1; s[nt][2] = p2; s[nt][3] = p3;
        }
        sum0 += __shfl_xor_sync(0xffffffffu, sum0, 1);
        sum0 += __shfl_xor_sync(0xffffffffu, sum0, 2);
        sum1 += __shfl_xor_sync(0xffffffffu, sum1, 1);
        sum1 += __shfl_xor_sync(0xffffffffu, sum1, 2);
        l0_ = l0_ * f0 + sum0; l1_ = l1_ * f1 + sum1;
        m0_ = mn0; m1_ = mn1;
#pragma unroll
        for (int nt = 0; nt < 8; nt++) {
            o[nt][0] *= f0; o[nt][1] *= f0;
            o[nt][2] *= f1; o[nt][3] *= f1;
        }

        // O += P V : repack S frags (C layout) into A frags in-register
#pragma unroll
        for (int c = 0; c < 4; c++) {
            uint32_t pa[4];
            pa[0] = packh2(s[2 * c][0], s[2 * c][1]);
            pa[1] = packh2(s[2 * c][2], s[2 * c][3]);
            pa[2] = packh2(s[2 * c + 1][0], s[2 * c + 1][1]);
            pa[3] = packh2(s[2 * c + 1][2], s[2 * c + 1][3]);
            uint32_t bf[4][4];
#pragma unroll
            for (int np = 0; np < 4; np++) ldsm4(bf[np], vbase + bofs[np] + c * 32);
#pragma unroll
            for (int np = 0; np < 4; np++) {
                mma16(o[2 * np],     pa, bf[np][0], bf[np][1]);
                mma16(o[2 * np + 1], pa, bf[np][2], bf[np][3]);
            }
        }

        __syncthreads();   // all reads of this stage done before ring reuse
        if (kt + 2 <= kt_end) issueKV(kt + 2);
    }

    // Normalize, convert, write g_y [B,T,E]
    float inv0 = 1.f / l0_, inv1 = 1.f / l1_;
    int t0 = q0 + warp * 16 + g;
#pragma unroll
    for (int nt = 0; nt < 8; nt++) {
        int col = h * 64 + nt * 8 + 2 * tg;
        *(__half2*)&g_y[((size_t)bb * TT + t0) * EE + col] =
            __floats2half2_rn(o[nt][0] * inv0, o[nt][1] * inv0);
        *(__half2*)&g_y[((size_t)bb * TT + t0 + 8) * EE + col] =
            __floats2half2_rn(o[nt][2] * inv1, o[nt][3] * inv1);
    }
}

// ---------------------------------------------------------------------------
extern "C" void kernel_launch(void* const* d_in, const int* in_sizes, int n_in,
                              void* d_out, int out_size)
{
    (void)in_sizes; (void)n_in; (void)out_size;
    const float* x      = (const float*)d_in[0];
    const float* W_attn = (const float*)d_in[1];
    const float* b_attn = (const float*)d_in[2];
    const float* W_proj = (const float*)d_in[3];
    const float* b_proj = (const float*)d_in[4];
    float* out = (float*)d_out;

    __half *xt, *wta, *wtp, *yv;
    cudaGetSymbolAddress((void**)&xt, g_xt);
    cudaGetSymbolAddress((void**)&wta, g_wta);
    cudaGetSymbolAddress((void**)&wtp, g_wtp);
    cudaGetSymbolAddress((void**)&yv, g_y);

    // 0) Convert X to half; transpose + convert weights
    cvt_x_kernel<<<(MM * EE) / (256 * 8), 256>>>(x, xt);
    transpose_cvt_kernel<<<dim3(N_QKV / 32, EE / 32), 256>>>(W_attn, wta, EE, N_QKV);
    transpose_cvt_kernel<<<dim3(EE / 32, EE / 32), 256>>>(W_proj, wtp, EE, EE);

    // 1) QKV projection -> g_q/g_k/g_vt (q scaled by 0.125*log2e; V transposed)
    cudaFuncSetAttribute(gemm_tc_kernel<0>,
                         cudaFuncAttributeMaxDynamicSharedMemorySize, GEMM_SMEM);
    gemm_tc_kernel<0><<<dim3(N_QKV / 128, MM / 128), 256, GEMM_SMEM>>>(
        xt, wta, b_attn, nullptr);

    // 2) Causal flash attention -> g_y
    cudaFuncSetAttribute(attn_tc_kernel,
                         cudaFuncAttributeMaxDynamicSharedMemorySize, ATT_SMEM);
    attn_tc_kernel<<<dim3(TT / 128, HH, BB), 256, ATT_SMEM>>>();

    // 3) Output projection -> d_out (fp32)
    cudaFuncSetAttribute(gemm_tc_kernel<1>,
                         cudaFuncAttributeMaxDynamicSharedMemorySize, GEMM_SMEM);
    gemm_tc_kernel<1><<<dim3(EE / 128, MM / 128), 256, GEMM_SMEM>>>(
        yv, wtp, b_proj, out);
}

// round 8
// speedup vs baseline: 11.8373x; 1.0255x over previous
#include <cuda_runtime.h>
#include <cuda_fp16.h>
#include <cstdint>

// Problem constants
#define BB 2
#define TT 4096
#define EE 768
#define HH 12
#define DD 64
#define MM (BB * TT)        // 8192
#define N_QKV (3 * EE)      // 2304
#define KTOT 768
#define LOG2E 1.4426950408889634f

// Scratch (allocation-free rule: __device__ globals), all fp16
__device__ __half g_q[(size_t)BB * HH * TT * DD];   // [B,H,T,D], scaled 0.125*log2e
__device__ __half g_k[(size_t)BB * HH * TT * DD];   // [B,H,T,D]
__device__ __half g_v[(size_t)BB * HH * TT * DD];   // [B,H,T,D]
__device__ __half g_y[(size_t)BB * TT * EE];        // [B,T,E]
__device__ __half g_xt[(size_t)MM * EE];            // X as half
__device__ __half g_wta[(size_t)N_QKV * EE];        // W_attn^T [2304][768]
__device__ __half g_wtp[(size_t)EE * EE];           // W_proj^T [768][768]

// ---------------------------------------------------------------------------
// Helpers
// ---------------------------------------------------------------------------
__device__ __forceinline__ uint32_t smem_u32(const void* p) {
    uint32_t a;
    asm("{ .reg .u64 t; cvta.to.shared.u64 t, %1; cvt.u32.u64 %0, t; }"
        : "=r"(a) : "l"(p));
    return a;
}
__device__ __forceinline__ void cp16(uint32_t dst, const void* src) {
    asm volatile("cp.async.cg.shared.global [%0], [%1], 16;"
                 :: "r"(dst), "l"(src) : "memory");
}
__device__ __forceinline__ void cp_commit() {
    asm volatile("cp.async.commit_group;" ::: "memory");
}
template<int N> __device__ __forceinline__ void cp_wait() {
    asm volatile("cp.async.wait_group %0;" :: "n"(N) : "memory");
}
__device__ __forceinline__ uint32_t packh2(float a, float b) {
    __half2 h = __floats2half2_rn(a, b);
    return *(uint32_t*)&h;
}
// ldmatrix x4: four 8x8 b16 mats; lane l addresses row l%8 of mat l/8.
__device__ __forceinline__ void ldsm4(uint32_t* r, uint32_t addr) {
    asm volatile("ldmatrix.sync.aligned.m8n8.x4.shared.b16 {%0,%1,%2,%3}, [%4];"
                 : "=r"(r[0]), "=r"(r[1]), "=r"(r[2]), "=r"(r[3]) : "r"(addr));
}
// transposed variant: fragment = transpose of each stored 8x8 (b16)
__device__ __forceinline__ void ldsm4t(uint32_t* r, uint32_t addr) {
    asm volatile("ldmatrix.sync.aligned.m8n8.x4.trans.shared.b16 {%0,%1,%2,%3}, [%4];"
                 : "=r"(r[0]), "=r"(r[1]), "=r"(r[2]), "=r"(r[3]) : "r"(addr));
}

// mma.sync m16n8k16 f16 -> f32.
__device__ __forceinline__ void mma16(float* c, const uint32_t* a,
                                      uint32_t b0, uint32_t b1) {
    asm volatile(
        "mma.sync.aligned.m16n8k16.row.col.f32.f16.f16.f32 "
        "{%0,%1,%2,%3}, {%4,%5,%6,%7}, {%8,%9}, {%0,%1,%2,%3};\n"
        : "+f"(c[0]), "+f"(c[1]), "+f"(c[2]), "+f"(c[3])
        : "r"(a[0]), "r"(a[1]), "r"(a[2]), "r"(a[3]), "r"(b0), "r"(b1));
}

extern __shared__ uint32_t dyn_smem[];

// ---------------------------------------------------------------------------
// Prep kernels
// ---------------------------------------------------------------------------
__global__ __launch_bounds__(256) void cvt_x_kernel(const float* __restrict__ src,
                                                    __half* __restrict__ dst) {
    size_t i = ((size_t)blockIdx.x * 256 + threadIdx.x) * 8;
    float4 v0 = *(const float4*)&src[i];
    float4 v1 = *(const float4*)&src[i + 4];
    uint4 o;
    o.x = packh2(v0.x, v0.y);
    o.y = packh2(v0.z, v0.w);
    o.z = packh2(v1.x, v1.y);
    o.w = packh2(v1.z, v1.w);
    *(uint4*)&dst[i] = o;
}

// dst[n][k] = half(src[k][n])
__global__ __launch_bounds__(256) void transpose_cvt_kernel(
    const float* __restrict__ src, __half* __restrict__ dst, int K, int N)
{
    __shared__ float t[32][33];
    const int n0 = blockIdx.x * 32, k0 = blockIdx.y * 32;
    const int tx = threadIdx.x & 31, ty = threadIdx.x >> 5;   // 32 x 8
#pragma unroll
    for (int j = 0; j < 4; j++)
        t[ty + j * 8][tx] = src[(size_t)(k0 + ty + j * 8) * N + n0 + tx];
    __syncthreads();
#pragma unroll
    for (int j = 0; j < 4; j++)
        dst[(size_t)(n0 + ty + j * 8) * K + k0 + tx] =
            __float2half_rn(t[tx][ty + j * 8]);
}

// ---------------------------------------------------------------------------
// fp16 tensor-core GEMM, cp.async 3-stage single-sync pipeline, LDSM frags.
// C = A[m][k] @ Bt[n][k]^T + bias.  Block 128x128, BK=64 halfs, 8 warps
// (4m x 2n), warp tile m32 x n64.  smem rows padded to 36 words (144 B).
// MODE 0: qkv scatter epilogue (q scaled by 0.125*log2e).  MODE 1: fp32 out.
// ---------------------------------------------------------------------------
#define BKH 64
#define NKT (KTOT / BKH)        // 12
#define TILE_W 36
#define HALF_ST (128 * TILE_W)        // words per A (or B) buffer
#define STAGE_WORDS (2 * HALF_ST)     // 9216 words per stage (A then B)
#define GEMM_SMEM (3 * STAGE_WORDS * 4)  // 110592 B

template<int MODE>
__global__ __launch_bounds__(256, 2) void gemm_tc_kernel(
    const __half* __restrict__ A, const __half* __restrict__ Bt,
    const float* __restrict__ bias, float* __restrict__ out)
{
    uint32_t* sm = dyn_smem;
    const uint32_t sb = smem_u32(sm);
    const int tid = threadIdx.x;
    const int warp = tid >> 5, lane = tid & 31;
    const int g = lane >> 2, tg = lane & 3;
    const int wm = warp >> 1, wn = warp & 1;
    const int m0 = blockIdx.y * 128, n0 = blockIdx.x * 128;
    const int m0w = wm * 32, n0w = wn * 64;

    // cp.async staging
    const int lr = tid >> 1;                 // load row 0..127
    const int cb = (tid & 1) * 4;            // chunk base (16B chunks)
    const __half* asrc0 = A + (size_t)(m0 + lr) * KTOT + cb * 8;
    const __half* bsrc0 = Bt + (size_t)(n0 + lr) * KTOT + cb * 8;
    const uint32_t adst0 = sb + (lr * TILE_W + cb * 4) * 4;
    const uint32_t bdst0 = sb + (HALF_ST + lr * TILE_W + cb * 4) * 4;

    // LDSM per-lane base offsets (within a stage)
    const int mt = lane >> 3, mr = lane & 7;
    uint32_t aoff[2];
#pragma unroll
    for (int mi = 0; mi < 2; mi++)
        aoff[mi] = ((m0w + mi * 16 + (mt & 1) * 8 + mr) * TILE_W + (mt >> 1) * 4) * 4;
    uint32_t boff[4];
#pragma unroll
    for (int np = 0; np < 4; np++)
        boff[np] = (HALF_ST + (n0w + np * 16 + (mt >> 1) * 8 + mr) * TILE_W
                    + (mt & 1) * 4) * 4;

    float acc[2][8][4];
#pragma unroll
    for (int mi = 0; mi < 2; mi++)
#pragma unroll
        for (int nt = 0; nt < 8; nt++)
#pragma unroll
            for (int j = 0; j < 4; j++) acc[mi][nt][j] = 0.f;

    auto issue = [&](int i) {
        const int s = i % 3;
        const int k0 = i * BKH;
        const uint32_t so = (uint32_t)(s * STAGE_WORDS * 4);
#pragma unroll
        for (int j = 0; j < 4; j++) {
            cp16(adst0 + so + j * 16, asrc0 + k0 + j * 8);
            cp16(bdst0 + so + j * 16, bsrc0 + k0 + j * 8);
        }
        cp_commit();
    };

    issue(0);
    issue(1);
    for (int i = 0; i < NKT; i++) {
        if (i + 1 < NKT) cp_wait<1>(); else cp_wait<0>();
        __syncthreads();
        if (i + 2 < NKT) issue(i + 2);   // writes stage (i-1)%3: readers done

        const uint32_t soff = sb + (uint32_t)((i % 3) * STAGE_WORDS * 4);
#pragma unroll
        for (int ks = 0; ks < 4; ks++) {
            const uint32_t ko = soff + ks * 32;        // 16 halfs = 32 B per ks
            uint32_t af[2][4], bf[4][4];
            ldsm4(af[0], aoff[0] + ko);
            ldsm4(af[1], aoff[1] + ko);
#pragma unroll
            for (int np = 0; np < 4; np++) ldsm4(bf[np], boff[np] + ko);
#pragma unroll
            for (int np = 0; np < 4; np++) {
                mma16(acc[0][2 * np],     af[0], bf[np][0], bf[np][1]);
                mma16(acc[0][2 * np + 1], af[0], bf[np][2], bf[np][3]);
                mma16(acc[1][2 * np],     af[1], bf[np][0], bf[np][1]);
                mma16(acc[1][2 * np + 1], af[1], bf[np][2], bf[np][3]);
            }
        }
    }

    // Epilogue
#pragma unroll
    for (int mi = 0; mi < 2; mi++)
#pragma unroll
        for (int hi = 0; hi < 2; hi++) {
            int gm = m0 + m0w + mi * 16 + hi * 8 + g;
#pragma unroll
            for (int nt = 0; nt < 8; nt++) {
                int gn = n0 + n0w + nt * 8 + 2 * tg;
                float v0 = acc[mi][nt][hi * 2] + bias[gn];
                float v1 = acc[mi][nt][hi * 2 + 1] + bias[gn + 1];
                if (MODE == 0) {
                    int bbv = gm >> 12;
                    int t = gm & (TT - 1);
                    int part = gn / EE;
                    int rem = gn - part * EE;
                    int hh = rem >> 6, d = rem & 63;
                    float sc = (part == 0) ? (0.125f * LOG2E) : 1.0f;
                    __half* dst = (part == 0) ? g_q : ((part == 1) ? g_k : g_v);
                    __half2 h = __floats2half2_rn(v0 * sc, v1 * sc);
                    *(__half2*)&dst[(((size_t)bbv * HH + hh) * TT + t) * DD + d] = h;
                } else {
                    *(float2*)&out[(size_t)gm * EE + gn] = make_float2(v0, v1);
                }
            }
        }
}

// ---------------------------------------------------------------------------
// Causal flash attention, fp16 mma + LDSM (V via ldmatrix.trans), exp2
// softmax, P in registers.  Grid: (T/128, H, B) with heavy tiles first,
// 256 threads (8 warps), warp tile m16 x kv64.  3-stage cp.async K/V ring,
// ONE __syncthreads per kv tile.
// smem words: Q[128*36] + 3 stages of (K[64*36] + V[64*36]).
// ---------------------------------------------------------------------------
#define AT_W 36
#define QS_WORDS (128 * AT_W)       // 4608
#define KV_WORDS (64 * AT_W)        // 2304
#define STAGE_W (2 * KV_WORDS)      // 4608
#define ATT_SMEM ((QS_WORDS + 3 * STAGE_W) * 4)   // 73728 B

__global__ __launch_bounds__(256, 2) void attn_tc_kernel()
{
    uint32_t* sm = dyn_smem;
    const uint32_t sb = smem_u32(sm);

    const int tid = threadIdx.x;
    const int warp = tid >> 5, lane = tid & 31;
    const int g = lane >> 2, tg = lane & 3;
    const int qt = (TT / 128 - 1) - blockIdx.x;   // heavy (large qt) first
    const int h = blockIdx.y, bb = blockIdx.z;
    const int q0 = qt * 128;

    const size_t hb = (size_t)bb * HH + h;
    const __half* qp = g_q + hb * TT * DD;
    const __half* kp = g_k + hb * TT * DD;
    const __half* vp = g_v + hb * TT * DD;

    // Issue Q tile (128 rows x 64 halfs) -> Qs   [group 0]
#pragma unroll
    for (int i = 0; i < 4; i++) {
        int idx = i * 256 + tid;
        int row = idx >> 3, c = idx & 7;
        cp16(sb + (row * AT_W + c * 4) * 4, qp + (size_t)(q0 + row) * DD + c * 8);
    }
    cp_commit();

    auto issueKV = [&](int kt) {
        const int st = kt % 3;
        const uint32_t base = sb + (QS_WORDS + st * STAGE_W) * 4;
#pragma unroll
        for (int i = 0; i < 4; i++) {
            int idx = i * 256 + tid;
            if (idx < 512) {                    // K rows (kv)
                int row = idx >> 3, c = idx & 7;
                cp16(base + (row * AT_W + c * 4) * 4,
                     kp + (size_t)(kt * 64 + row) * DD + c * 8);
            } else {                            // V rows (kv), same layout
                int j = idx - 512;
                int row = j >> 3, c = j & 7;
                cp16(base + (KV_WORDS + row * AT_W + c * 4) * 4,
                     vp + (size_t)(kt * 64 + row) * DD + c * 8);
            }
        }
        cp_commit();
    };

    const int kt_end = 2 * qt + 1;   // inclusive; >= 1 always
    issueKV(0);
    issueKV(1);

    // Wait for Q (oldest group), build Q fragments with LDSM
    cp_wait<2>();
    __syncthreads();

    const int mt = lane >> 3, mr = lane & 7;
    uint32_t qf[4][4];
    {
        const uint32_t qrow = sb + ((warp * 16 + (mt & 1) * 8 + mr) * AT_W) * 4;
#pragma unroll
        for (int c = 0; c < 4; c++)
            ldsm4(qf[c], qrow + (c * 8 + (mt >> 1) * 4) * 4);
    }
    // K B-frag per-lane offsets (within a K tile): rows = kv (n), cols = d (k)
    uint32_t bofs[4];
#pragma unroll
    for (int np = 0; np < 4; np++)
        bofs[np] = ((np * 16 + (mt >> 1) * 8 + mr) * AT_W + (mt & 1) * 4) * 4;
    // V B-frag per-lane offsets (trans ldsm): rows = kv (k), cols = d (n).
    // Mat order per x4: [k0-7,n0-7] [k8-15,n0-7] [k0-7,n8-15] [k8-15,n8-15]
    uint32_t vofs[4];
#pragma unroll
    for (int np = 0; np < 4; np++)
        vofs[np] = (((mt & 1) * 8 + mr) * AT_W + np * 8 + (mt >> 1) * 4) * 4;

    float o[8][4];
    float m0_ = -1e30f, m1_ = -1e30f, l0_ = 0.f, l1_ = 0.f;
#pragma unroll
    for (int nt = 0; nt < 8; nt++)
#pragma unroll
        for (int j = 0; j < 4; j++) o[nt][j] = 0.f;

    for (int kt = 0; kt <= kt_end; kt++) {
        if (kt + 1 <= kt_end) cp_wait<1>(); else cp_wait<0>();
        __syncthreads();
        if (kt + 2 <= kt_end) issueKV(kt + 2);   // stage (kt-1)%3: readers done

        const uint32_t kbase = sb + (QS_WORDS + (kt % 3) * STAGE_W) * 4;
        const uint32_t vbase = kbase + KV_WORDS * 4;

        // S = Q K^T  (16 x 64 per warp), log2-domain scores
        float s[8][4];
#pragma unroll
        for (int nt = 0; nt < 8; nt++)
#pragma unroll
            for (int j = 0; j < 4; j++) s[nt][j] = 0.f;
#pragma unroll
        for (int c = 0; c < 4; c++) {
            uint32_t bf[4][4];
#pragma unroll
            for (int np = 0; np < 4; np++) ldsm4(bf[np], kbase + bofs[np] + c * 32);
#pragma unroll
            for (int np = 0; np < 4; np++) {
                mma16(s[2 * np],     qf[c], bf[np][0], bf[np][1]);
                mma16(s[2 * np + 1], qf[c], bf[np][2], bf[np][3]);
            }
        }

        // Causal mask (diagonal-overlapping tiles only)
        if (kt >= 2 * qt) {
            int row0 = q0 + warp * 16 + g;
#pragma unroll
            for (int nt = 0; nt < 8; nt++) {
                int col = kt * 64 + nt * 8 + 2 * tg;
                if (col > row0)     s[nt][0] = -1e30f;
                if (col + 1 > row0) s[nt][1] = -1e30f;
                if (col > row0 + 8)     s[nt][2] = -1e30f;
                if (col + 1 > row0 + 8) s[nt][3] = -1e30f;
            }
        }

        // Online softmax (base-2) for rows g and g+8
        float mx0 = -1e30f, mx1 = -1e30f;
#pragma unroll
        for (int nt = 0; nt < 8; nt++) {
            mx0 = fmaxf(mx0, fmaxf(s[nt][0], s[nt][1]));
            mx1 = fmaxf(mx1, fmaxf(s[nt][2], s[nt][3]));
        }
        mx0 = fmaxf(mx0, __shfl_xor_sync(0xffffffffu, mx0, 1));
        mx0 = fmaxf(mx0, __shfl_xor_sync(0xffffffffu, mx0, 2));
        mx1 = fmaxf(mx1, __shfl_xor_sync(0xffffffffu, mx1, 1));
        mx1 = fmaxf(mx1, __shfl_xor_sync(0xffffffffu, mx1, 2));
        float mn0 = fmaxf(m0_, mx0), mn1 = fmaxf(m1_, mx1);
        float f0 = exp2f(m0_ - mn0), f1 = exp2f(m1_ - mn1);
        float sum0 = 0.f, sum1 = 0.f;
#pragma unroll
        for (int nt = 0; nt < 8; nt++) {
            float p0 = exp2f(s[nt][0] - mn0);
            float p1 = exp2f(s[nt][1] - mn0);
            float p2 = exp2f(s[nt][2] - mn1);
            float p3 = exp2f(s[nt][3] - mn1);
            sum0 += p0 + p1; sum1 += p2 + p3;
            s[nt][0] = p0; s[nt][1] = p1; s[nt][2] = p2; s[nt][3] = p3;
        }
        sum0 += __shfl_xor_sync(0xffffffffu, sum0, 1);
        sum0 += __shfl_xor_sync(0xffffffffu, sum0, 2);
        sum1 += __shfl_xor_sync(0xffffffffu, sum1, 1);
        sum1 += __shfl_xor_sync(0xffffffffu, sum1, 2);
        l0_ = l0_ * f0 + sum0; l1_ = l1_ * f1 + sum1;
        m0_ = mn0; m1_ = mn1;
#pragma unroll
        for (int nt = 0; nt < 8; nt++) {
            o[nt][0] *= f0; o[nt][1] *= f0;
            o[nt][2] *= f1; o[nt][3] *= f1;
        }

        // O += P V : repack S frags (C layout) into A frags in-register;
        // V B-frags via transposed ldmatrix on [kv][d] tile.
#pragma unroll
        for (int c = 0; c < 4; c++) {
            uint32_t pa[4];
            pa[0] = packh2(s[2 * c][0], s[2 * c][1]);
            pa[1] = packh2(s[2 * c][2], s[2 * c][3]);
            pa[2] = packh2(s[2 * c + 1][0], s[2 * c + 1][1]);
            pa[3] = packh2(s[2 * c + 1][2], s[2 * c + 1][3]);
            uint32_t bf[4][4];
#pragma unroll
            for (int np = 0; np < 4; np++)
                ldsm4t(bf[np], vbase + vofs[np] + c * 16 * AT_W * 4);
#pragma unroll
            for (int np = 0; np < 4; np++) {
                mma16(o[2 * np],     pa, bf[np][0], bf[np][1]);
                mma16(o[2 * np + 1], pa, bf[np][2], bf[np][3]);
            }
        }
    }

    // Normalize, convert, write g_y [B,T,E]
    float inv0 = 1.f / l0_, inv1 = 1.f / l1_;
    int t0 = q0 + warp * 16 + g;
#pragma unroll
    for (int nt = 0; nt < 8; nt++) {
        int col = h * 64 + nt * 8 + 2 * tg;
        *(__half2*)&g_y[((size_t)bb * TT + t0) * EE + col] =
            __floats2half2_rn(o[nt][0] * inv0, o[nt][1] * inv0);
        *(__half2*)&g_y[((size_t)bb * TT + t0 + 8) * EE + col] =
            __floats2half2_rn(o[nt][2] * inv1, o[nt][3] * inv1);
    }
}

// ---------------------------------------------------------------------------
extern "C" void kernel_launch(void* const* d_in, const int* in_sizes, int n_in,
                              void* d_out, int out_size)
{
    (void)in_sizes; (void)n_in; (void)out_size;
    const float* x      = (const float*)d_in[0];
    const float* W_attn = (const float*)d_in[1];
    const float* b_attn = (const float*)d_in[2];
    const float* W_proj = (const float*)d_in[3];
    const float* b_proj = (const float*)d_in[4];
    float* out = (float*)d_out;

    __half *xt, *wta, *wtp, *yv;
    cudaGetSymbolAddress((void**)&xt, g_xt);
    cudaGetSymbolAddress((void**)&wta, g_wta);
    cudaGetSymbolAddress((void**)&wtp, g_wtp);
    cudaGetSymbolAddress((void**)&yv, g_y);

    // 0) Convert X to half; transpose + convert weights
    cvt_x_kernel<<<(MM * EE) / (256 * 8), 256>>>(x, xt);
    transpose_cvt_kernel<<<dim3(N_QKV / 32, EE / 32), 256>>>(W_attn, wta, EE, N_QKV);
    transpose_cvt_kernel<<<dim3(EE / 32, EE / 32), 256>>>(W_proj, wtp, EE, EE);

    // 1) QKV projection -> g_q/g_k/g_v (q scaled by 0.125*log2e)
    cudaFuncSetAttribute(gemm_tc_kernel<0>,
                         cudaFuncAttributeMaxDynamicSharedMemorySize, GEMM_SMEM);
    gemm_tc_kernel<0><<<dim3(N_QKV / 128, MM / 128), 256, GEMM_SMEM>>>(
        xt, wta, b_attn, nullptr);

    // 2) Causal flash attention -> g_y
    cudaFuncSetAttribute(attn_tc_kernel,
                         cudaFuncAttributeMaxDynamicSharedMemorySize, ATT_SMEM);
    attn_tc_kernel<<<dim3(TT / 128, HH, BB), 256, ATT_SMEM>>>();

    // 3) Output projection -> d_out (fp32)
    cudaFuncSetAttribute(gemm_tc_kernel<1>,
                         cudaFuncAttributeMaxDynamicSharedMemorySize, GEMM_SMEM);
    gemm_tc_kernel<1><<<dim3(EE / 128, MM / 128), 256, GEMM_SMEM>>>(
        yv, wtp, b_proj, out);
}

// round 9
// speedup vs baseline: 12.5229x; 1.0579x over previous
#include <cuda_runtime.h>
#include <cuda_fp16.h>
#include <cstdint>

// Problem constants
#define BB 2
#define TT 4096
#define EE 768
#define HH 12
#define DD 64
#define MM (BB * TT)        // 8192
#define N_QKV (3 * EE)      // 2304
#define KTOT 768
#define LOG2E 1.4426950408889634f

// Scratch (allocation-free rule: __device__ globals), all fp16
__device__ __half g_q[(size_t)BB * HH * TT * DD];   // [B,H,T,D], scaled 0.125*log2e
__device__ __half g_k[(size_t)BB * HH * TT * DD];   // [B,H,T,D]
__device__ __half g_v[(size_t)BB * HH * TT * DD];   // [B,H,T,D]
__device__ __half g_y[(size_t)BB * TT * EE];        // [B,T,E]
__device__ __half g_xt[(size_t)MM * EE];            // X as half
__device__ __half g_wta[(size_t)N_QKV * EE];        // W_attn^T [2304][768]
__device__ __half g_wtp[(size_t)EE * EE];           // W_proj^T [768][768]

// ---------------------------------------------------------------------------
// Helpers
// ---------------------------------------------------------------------------
__device__ __forceinline__ uint32_t smem_u32(const void* p) {
    uint32_t a;
    asm("{ .reg .u64 t; cvta.to.shared.u64 t, %1; cvt.u32.u64 %0, t; }"
        : "=r"(a) : "l"(p));
    return a;
}
__device__ __forceinline__ void cp16(uint32_t dst, const void* src) {
    asm volatile("cp.async.cg.shared.global [%0], [%1], 16;"
                 :: "r"(dst), "l"(src) : "memory");
}
__device__ __forceinline__ void cp_commit() {
    asm volatile("cp.async.commit_group;" ::: "memory");
}
template<int N> __device__ __forceinline__ void cp_wait() {
    asm volatile("cp.async.wait_group %0;" :: "n"(N) : "memory");
}
__device__ __forceinline__ uint32_t packh2(float a, float b) {
    __half2 h = __floats2half2_rn(a, b);
    return *(uint32_t*)&h;
}
__device__ __forceinline__ uint32_t ex2_h2(uint32_t x) {   // 2x half exp2, 1 MUFU
    uint32_t r;
    asm("ex2.approx.f16x2 %0, %1;" : "=r"(r) : "r"(x));
    return r;
}
// ldmatrix x4: four 8x8 b16 mats; lane l addresses row l%8 of mat l/8.
__device__ __forceinline__ void ldsm4(uint32_t* r, uint32_t addr) {
    asm volatile("ldmatrix.sync.aligned.m8n8.x4.shared.b16 {%0,%1,%2,%3}, [%4];"
                 : "=r"(r[0]), "=r"(r[1]), "=r"(r[2]), "=r"(r[3]) : "r"(addr));
}
// transposed variant: fragment = transpose of each stored 8x8 (b16)
__device__ __forceinline__ void ldsm4t(uint32_t* r, uint32_t addr) {
    asm volatile("ldmatrix.sync.aligned.m8n8.x4.trans.shared.b16 {%0,%1,%2,%3}, [%4];"
                 : "=r"(r[0]), "=r"(r[1]), "=r"(r[2]), "=r"(r[3]) : "r"(addr));
}

// mma.sync m16n8k16 f16 -> f32.
__device__ __forceinline__ void mma16(float* c, const uint32_t* a,
                                      uint32_t b0, uint32_t b1) {
    asm volatile(
        "mma.sync.aligned.m16n8k16.row.col.f32.f16.f16.f32 "
        "{%0,%1,%2,%3}, {%4,%5,%6,%7}, {%8,%9}, {%0,%1,%2,%3};\n"
        : "+f"(c[0]), "+f"(c[1]), "+f"(c[2]), "+f"(c[3])
        : "r"(a[0]), "r"(a[1]), "r"(a[2]), "r"(a[3]), "r"(b0), "r"(b1));
}

extern __shared__ uint32_t dyn_smem[];

// ---------------------------------------------------------------------------
// Prep kernels
// ---------------------------------------------------------------------------
__global__ __launch_bounds__(256) void cvt_x_kernel(const float* __restrict__ src,
                                                    __half* __restrict__ dst) {
    size_t i = ((size_t)blockIdx.x * 256 + threadIdx.x) * 8;
    float4 v0 = *(const float4*)&src[i];
    float4 v1 = *(const float4*)&src[i + 4];
    uint4 o;
    o.x = packh2(v0.x, v0.y);
    o.y = packh2(v0.z, v0.w);
    o.z = packh2(v1.x, v1.y);
    o.w = packh2(v1.z, v1.w);
    *(uint4*)&dst[i] = o;
}

// dst[n][k] = half(src[k][n])
__global__ __launch_bounds__(256) void transpose_cvt_kernel(
    const float* __restrict__ src, __half* __restrict__ dst, int K, int N)
{
    __shared__ float t[32][33];
    const int n0 = blockIdx.x * 32, k0 = blockIdx.y * 32;
    const int tx = threadIdx.x & 31, ty = threadIdx.x >> 5;   // 32 x 8
#pragma unroll
    for (int j = 0; j < 4; j++)
        t[ty + j * 8][tx] = src[(size_t)(k0 + ty + j * 8) * N + n0 + tx];
    __syncthreads();
#pragma unroll
    for (int j = 0; j < 4; j++)
        dst[(size_t)(n0 + ty + j * 8) * K + k0 + tx] =
            __float2half_rn(t[tx][ty + j * 8]);
}

// ---------------------------------------------------------------------------
// fp16 tensor-core GEMM, cp.async 3-stage single-sync pipeline, LDSM frags.
// C = A[m][k] @ Bt[n][k]^T + bias.  Block 128x128, BK=64 halfs, 8 warps
// (4m x 2n), warp tile m32 x n64.  smem rows padded to 36 words (144 B).
// MODE 0: qkv epilogue staged through smem for coalesced scatter.
// MODE 1: fp32 linear out (already full-sector stores).
// ---------------------------------------------------------------------------
#define BKH 64
#define NKT (KTOT / BKH)        // 12
#define TILE_W 36
#define HALF_ST (128 * TILE_W)        // words per A (or B) buffer
#define STAGE_WORDS (2 * HALF_ST)     // 9216 words per stage (A then B)
#define GEMM_SMEM (3 * STAGE_WORDS * 4)  // 110592 B
#define CS_HW 136                      // C-stage row stride in halfs (68 words)

template<int MODE>
__global__ __launch_bounds__(256, 2) void gemm_tc_kernel(
    const __half* __restrict__ A, const __half* __restrict__ Bt,
    const float* __restrict__ bias, float* __restrict__ out)
{
    uint32_t* sm = dyn_smem;
    const uint32_t sb = smem_u32(sm);
    const int tid = threadIdx.x;
    const int warp = tid >> 5, lane = tid & 31;
    const int g = lane >> 2, tg = lane & 3;
    const int wm = warp >> 1, wn = warp & 1;
    const int m0 = blockIdx.y * 128, n0 = blockIdx.x * 128;
    const int m0w = wm * 32, n0w = wn * 64;

    // cp.async staging
    const int lr = tid >> 1;                 // load row 0..127
    const int cb = (tid & 1) * 4;            // chunk base (16B chunks)
    const __half* asrc0 = A + (size_t)(m0 + lr) * KTOT + cb * 8;
    const __half* bsrc0 = Bt + (size_t)(n0 + lr) * KTOT + cb * 8;
    const uint32_t adst0 = sb + (lr * TILE_W + cb * 4) * 4;
    const uint32_t bdst0 = sb + (HALF_ST + lr * TILE_W + cb * 4) * 4;

    // LDSM per-lane base offsets (within a stage)
    const int mt = lane >> 3, mr = lane & 7;
    uint32_t aoff[2];
#pragma unroll
    for (int mi = 0; mi < 2; mi++)
        aoff[mi] = ((m0w + mi * 16 + (mt & 1) * 8 + mr) * TILE_W + (mt >> 1) * 4) * 4;
    uint32_t boff[4];
#pragma unroll
    for (int np = 0; np < 4; np++)
        boff[np] = (HALF_ST + (n0w + np * 16 + (mt >> 1) * 8 + mr) * TILE_W
                    + (mt & 1) * 4) * 4;

    float acc[2][8][4];
#pragma unroll
    for (int mi = 0; mi < 2; mi++)
#pragma unroll
        for (int nt = 0; nt < 8; nt++)
#pragma unroll
            for (int j = 0; j < 4; j++) acc[mi][nt][j] = 0.f;

    auto issue = [&](int i) {
        const int s = i % 3;
        const int k0 = i * BKH;
        const uint32_t so = (uint32_t)(s * STAGE_WORDS * 4);
#pragma unroll
        for (int j = 0; j < 4; j++) {
            cp16(adst0 + so + j * 16, asrc0 + k0 + j * 8);
            cp16(bdst0 + so + j * 16, bsrc0 + k0 + j * 8);
        }
        cp_commit();
    };

    issue(0);
    issue(1);
    for (int i = 0; i < NKT; i++) {
        if (i + 1 < NKT) cp_wait<1>(); else cp_wait<0>();
        __syncthreads();
        if (i + 2 < NKT) issue(i + 2);   // writes stage (i-1)%3: readers done

        const uint32_t soff = sb + (uint32_t)((i % 3) * STAGE_WORDS * 4);
#pragma unroll
        for (int ks = 0; ks < 4; ks++) {
            const uint32_t ko = soff + ks * 32;        // 16 halfs = 32 B per ks
            uint32_t af[2][4], bf[4][4];
            ldsm4(af[0], aoff[0] + ko);
            ldsm4(af[1], aoff[1] + ko);
#pragma unroll
            for (int np = 0; np < 4; np++) ldsm4(bf[np], boff[np] + ko);
#pragma unroll
            for (int np = 0; np < 4; np++) {
                mma16(acc[0][2 * np],     af[0], bf[np][0], bf[np][1]);
                mma16(acc[0][2 * np + 1], af[0], bf[np][2], bf[np][3]);
                mma16(acc[1][2 * np],     af[1], bf[np][0], bf[np][1]);
                mma16(acc[1][2 * np + 1], af[1], bf[np][2], bf[np][3]);
            }
        }
    }

    if (MODE == 0) {
        // Stage C (bias+scale, half) into smem, then coalesced scatter.
        __half* Cs = (__half*)sm;
#pragma unroll
        for (int mi = 0; mi < 2; mi++)
#pragma unroll
            for (int hi = 0; hi < 2; hi++) {
                int lrow = m0w + mi * 16 + hi * 8 + g;
#pragma unroll
                for (int nt = 0; nt < 8; nt++) {
                    int lcol = n0w + nt * 8 + 2 * tg;
                    int gn = n0 + lcol;
                    float v0 = acc[mi][nt][hi * 2] + bias[gn];
                    float v1 = acc[mi][nt][hi * 2 + 1] + bias[gn + 1];
                    float sc = (gn < EE) ? (0.125f * LOG2E) : 1.0f;
                    *(__half2*)&Cs[lrow * CS_HW + lcol] =
                        __floats2half2_rn(v0 * sc, v1 * sc);
                }
            }
        __syncthreads();
#pragma unroll
        for (int it = 0; it < 8; it++) {
            int c = it * 256 + tid;            // 0..2047
            int row = c >> 4, seg = c & 15;    // 16B segments per row
            uint4 v = *(uint4*)&Cs[row * CS_HW + seg * 8];
            int gm = m0 + row, gn = n0 + seg * 8;
            int bbv = gm >> 12, t = gm & (TT - 1);
            int part = gn / EE;
            int rem = gn - part * EE;
            int hh = rem >> 6, d = rem & 63;
            __half* dst = (part == 0) ? g_q : ((part == 1) ? g_k : g_v);
            *(uint4*)&dst[(((size_t)bbv * HH + hh) * TT + t) * DD + d] = v;
        }
    } else {
#pragma unroll
        for (int mi = 0; mi < 2; mi++)
#pragma unroll
            for (int hi = 0; hi < 2; hi++) {
                int gm = m0 + m0w + mi * 16 + hi * 8 + g;
#pragma unroll
                for (int nt = 0; nt < 8; nt++) {
                    int gn = n0 + n0w + nt * 8 + 2 * tg;
                    float v0 = acc[mi][nt][hi * 2] + bias[gn];
                    float v1 = acc[mi][nt][hi * 2 + 1] + bias[gn + 1];
                    *(float2*)&out[(size_t)gm * EE + gn] = make_float2(v0, v1);
                }
            }
    }
}

// ---------------------------------------------------------------------------
// Causal flash attention, fp16 mma + LDSM (V via ldmatrix.trans), f16x2 exp2
// softmax, row-sum via ones-MMA, P in registers.  Grid: (T/128, H, B) heavy
// tiles first, 256 threads (8 warps), warp tile m16 x kv64.  3-stage cp.async
// K/V ring, ONE __syncthreads per kv tile.
// ---------------------------------------------------------------------------
#define AT_W 36
#define QS_WORDS (128 * AT_W)       // 4608
#define KV_WORDS (64 * AT_W)        // 2304
#define STAGE_W (2 * KV_WORDS)      // 4608
#define ATT_SMEM ((QS_WORDS + 3 * STAGE_W) * 4)   // 73728 B
#define ONES_H2 0x3C003C00u

__global__ __launch_bounds__(256, 2) void attn_tc_kernel()
{
    uint32_t* sm = dyn_smem;
    const uint32_t sb = smem_u32(sm);

    const int tid = threadIdx.x;
    const int warp = tid >> 5, lane = tid & 31;
    const int g = lane >> 2, tg = lane & 3;
    const int qt = (TT / 128 - 1) - blockIdx.x;   // heavy (large qt) first
    const int h = blockIdx.y, bb = blockIdx.z;
    const int q0 = qt * 128;

    const size_t hb = (size_t)bb * HH + h;
    const __half* qp = g_q + hb * TT * DD;
    const __half* kp = g_k + hb * TT * DD;
    const __half* vp = g_v + hb * TT * DD;

    // Issue Q tile (128 rows x 64 halfs) -> Qs   [group 0]
#pragma unroll
    for (int i = 0; i < 4; i++) {
        int idx = i * 256 + tid;
        int row = idx >> 3, c = idx & 7;
        cp16(sb + (row * AT_W + c * 4) * 4, qp + (size_t)(q0 + row) * DD + c * 8);
    }
    cp_commit();

    auto issueKV = [&](int kt) {
        const int st = kt % 3;
        const uint32_t base = sb + (QS_WORDS + st * STAGE_W) * 4;
#pragma unroll
        for (int i = 0; i < 4; i++) {
            int idx = i * 256 + tid;
            if (idx < 512) {                    // K rows (kv)
                int row = idx >> 3, c = idx & 7;
                cp16(base + (row * AT_W + c * 4) * 4,
                     kp + (size_t)(kt * 64 + row) * DD + c * 8);
            } else {                            // V rows (kv), same layout
                int j = idx - 512;
                int row = j >> 3, c = j & 7;
                cp16(base + (KV_WORDS + row * AT_W + c * 4) * 4,
                     vp + (size_t)(kt * 64 + row) * DD + c * 8);
            }
        }
        cp_commit();
    };

    const int kt_end = 2 * qt + 1;   // inclusive; >= 1 always
    issueKV(0);
    issueKV(1);

    // Wait for Q (oldest group), build Q fragments with LDSM
    cp_wait<2>();
    __syncthreads();

    const int mt = lane >> 3, mr = lane & 7;
    uint32_t qf[4][4];
    {
        const uint32_t qrow = sb + ((warp * 16 + (mt & 1) * 8 + mr) * AT_W) * 4;
#pragma unroll
        for (int c = 0; c < 4; c++)
            ldsm4(qf[c], qrow + (c * 8 + (mt >> 1) * 4) * 4);
    }
    // K B-frag per-lane offsets (within a K tile): rows = kv (n), cols = d (k)
    uint32_t bofs[4];
#pragma unroll
    for (int np = 0; np < 4; np++)
        bofs[np] = ((np * 16 + (mt >> 1) * 8 + mr) * AT_W + (mt & 1) * 4) * 4;
    // V B-frag per-lane offsets (trans ldsm): rows = kv (k), cols = d (n).
    uint32_t vofs[4];
#pragma unroll
    for (int np = 0; np < 4; np++)
        vofs[np] = (((mt & 1) * 8 + mr) * AT_W + np * 8 + (mt >> 1) * 4) * 4;

    float o[8][4];
    float osum[4] = {0.f, 0.f, 0.f, 0.f};   // P@ones accumulator (row sums)
    float m0_ = -1e30f, m1_ = -1e30f;
#pragma unroll
    for (int nt = 0; nt < 8; nt++)
#pragma unroll
        for (int j = 0; j < 4; j++) o[nt][j] = 0.f;

    for (int kt = 0; kt <= kt_end; kt++) {
        if (kt + 1 <= kt_end) cp_wait<1>(); else cp_wait<0>();
        __syncthreads();
        if (kt + 2 <= kt_end) issueKV(kt + 2);   // stage (kt-1)%3: readers done

        const uint32_t kbase = sb + (QS_WORDS + (kt % 3) * STAGE_W) * 4;
        const uint32_t vbase = kbase + KV_WORDS * 4;

        // S = Q K^T  (16 x 64 per warp), log2-domain scores
        float s[8][4];
#pragma unroll
        for (int nt = 0; nt < 8; nt++)
#pragma unroll
            for (int j = 0; j < 4; j++) s[nt][j] = 0.f;
#pragma unroll
        for (int c = 0; c < 4; c++) {
            uint32_t bf[4][4];
#pragma unroll
            for (int np = 0; np < 4; np++) ldsm4(bf[np], kbase + bofs[np] + c * 32);
#pragma unroll
            for (int np = 0; np < 4; np++) {
                mma16(s[2 * np],     qf[c], bf[np][0], bf[np][1]);
                mma16(s[2 * np + 1], qf[c], bf[np][2], bf[np][3]);
            }
        }

        // Causal mask (diagonal-overlapping tiles only)
        if (kt >= 2 * qt) {
            int row0 = q0 + warp * 16 + g;
#pragma unroll
            for (int nt = 0; nt < 8; nt++) {
                int col = kt * 64 + nt * 8 + 2 * tg;
                if (col > row0)     s[nt][0] = -1e30f;
                if (col + 1 > row0) s[nt][1] = -1e30f;
                if (col > row0 + 8)     s[nt][2] = -1e30f;
                if (col + 1 > row0 + 8) s[nt][3] = -1e30f;
            }
        }

        // Online softmax (base-2): max in f32, exp via f16x2 MUFU.
        float mx0 = -1e30f, mx1 = -1e30f;
#pragma unroll
        for (int nt = 0; nt < 8; nt++) {
            mx0 = fmaxf(mx0, fmaxf(s[nt][0], s[nt][1]));
            mx1 = fmaxf(mx1, fmaxf(s[nt][2], s[nt][3]));
        }
        mx0 = fmaxf(mx0, __shfl_xor_sync(0xffffffffu, mx0, 1));
        mx0 = fmaxf(mx0, __shfl_xor_sync(0xffffffffu, mx0, 2));
        mx1 = fmaxf(mx1, __shfl_xor_sync(0xffffffffu, mx1, 1));
        mx1 = fmaxf(mx1, __shfl_xor_sync(0xffffffffu, mx1, 2));
        float mn0 = fmaxf(m0_, mx0), mn1 = fmaxf(m1_, mx1);
        float f0 = exp2f(m0_ - mn0), f1 = exp2f(m1_ - mn1);
        m0_ = mn0; m1_ = mn1;

        // P = exp2(s - mn) as packed halves == PV A-fragments directly
        uint32_t pe[8][2];
#pragma unroll
        for (int nt = 0; nt < 8; nt++) {
            pe[nt][0] = ex2_h2(packh2(s[nt][0] - mn0, s[nt][1] - mn0));
            pe[nt][1] = ex2_h2(packh2(s[nt][2] - mn1, s[nt][3] - mn1));
        }

        // Rescale running O and row-sum accumulators
#pragma unroll
        for (int nt = 0; nt < 8; nt++) {
            o[nt][0] *= f0; o[nt][1] *= f0;
            o[nt][2] *= f1; o[nt][3] *= f1;
        }
        osum[0] *= f0; osum[1] *= f0; osum[2] *= f1; osum[3] *= f1;

        // O += P V  (+ row sums via ones-column mma)
#pragma unroll
        for (int c = 0; c < 4; c++) {
            uint32_t pa[4] = { pe[2 * c][0], pe[2 * c][1],
                               pe[2 * c + 1][0], pe[2 * c + 1][1] };
            mma16(osum, pa, ONES_H2, ONES_H2);
            uint32_t bf[4][4];
#pragma unroll
            for (int np = 0; np < 4; np++)
                ldsm4t(bf[np], vbase + vofs[np] + c * 16 * AT_W * 4);
#pragma unroll
            for (int np = 0; np < 4; np++) {
                mma16(o[2 * np],     pa, bf[np][0], bf[np][1]);
                mma16(o[2 * np + 1], pa, bf[np][2], bf[np][3]);
            }
        }
    }

    // Normalize, convert, write g_y [B,T,E]
    float inv0 = 1.f / osum[0], inv1 = 1.f / osum[2];
    int t0 = q0 + warp * 16 + g;
#pragma unroll
    for (int nt = 0; nt < 8; nt++) {
        int col = h * 64 + nt * 8 + 2 * tg;
        *(__half2*)&g_y[((size_t)bb * TT + t0) * EE + col] =
            __floats2half2_rn(o[nt][0] * inv0, o[nt][1] * inv0);
        *(__half2*)&g_y[((size_t)bb * TT + t0 + 8) * EE + col] =
            __floats2half2_rn(o[nt][2] * inv1, o[nt][3] * inv1);
    }
}

// ---------------------------------------------------------------------------
extern "C" void kernel_launch(void* const* d_in, const int* in_sizes, int n_in,
                              void* d_out, int out_size)
{
    (void)in_sizes; (void)n_in; (void)out_size;
    const float* x      = (const float*)d_in[0];
    const float* W_attn = (const float*)d_in[1];
    const float* b_attn = (const float*)d_in[2];
    const float* W_proj = (const float*)d_in[3];
    const float* b_proj = (const float*)d_in[4];
    float* out = (float*)d_out;

    __half *xt, *wta, *wtp, *yv;
    cudaGetSymbolAddress((void**)&xt, g_xt);
    cudaGetSymbolAddress((void**)&wta, g_wta);
    cudaGetSymbolAddress((void**)&wtp, g_wtp);
    cudaGetSymbolAddress((void**)&yv, g_y);

    // 0) Convert X to half; transpose + convert weights
    cvt_x_kernel<<<(MM * EE) / (256 * 8), 256>>>(x, xt);
    transpose_cvt_kernel<<<dim3(N_QKV / 32, EE / 32), 256>>>(W_attn, wta, EE, N_QKV);
    transpose_cvt_kernel<<<dim3(EE / 32, EE / 32), 256>>>(W_proj, wtp, EE, EE);

    // 1) QKV projection -> g_q/g_k/g_v (q scaled by 0.125*log2e)
    cudaFuncSetAttribute(gemm_tc_kernel<0>,
                         cudaFuncAttributeMaxDynamicSharedMemorySize, GEMM_SMEM);
    gemm_tc_kernel<0><<<dim3(N_QKV / 128, MM / 128), 256, GEMM_SMEM>>>(
        xt, wta, b_attn, nullptr);

    // 2) Causal flash attention -> g_y
    cudaFuncSetAttribute(attn_tc_kernel,
                         cudaFuncAttributeMaxDynamicSharedMemorySize, ATT_SMEM);
    attn_tc_kernel<<<dim3(TT / 128, HH, BB), 256, ATT_SMEM>>>();

    // 3) Output projection -> d_out (fp32)
    cudaFuncSetAttribute(gemm_tc_kernel<1>,
                         cudaFuncAttributeMaxDynamicSharedMemorySize, GEMM_SMEM);
    gemm_tc_kernel<1><<<dim3(EE / 128, MM / 128), 256, GEMM_SMEM>>>(
        yv, wtp, b_proj, out);
}

// round 11
// speedup vs baseline: 13.0851x; 1.0449x over previous
#include <cuda_runtime.h>
#include <cuda_fp16.h>
#include <cstdint>

// Problem constants
#define BB 2
#define TT 4096
#define EE 768
#define HH 12
#define DD 64
#define MM (BB * TT)        // 8192
#define N_QKV (3 * EE)      // 2304
#define KTOT 768
#define LOG2E 1.4426950408889634f

// Scratch (allocation-free rule: __device__ globals), all fp16
__device__ __half g_q[(size_t)BB * HH * TT * DD];   // [B,H,T,D], scaled 0.125*log2e
__device__ __half g_k[(size_t)BB * HH * TT * DD];   // [B,H,T,D]
__device__ __half g_v[(size_t)BB * HH * TT * DD];   // [B,H,T,D]
__device__ __half g_y[(size_t)BB * TT * EE];        // [B,T,E]
__device__ __half g_xt[(size_t)MM * EE];            // X as half
__device__ __half g_wta[(size_t)N_QKV * EE];        // W_attn^T [2304][768]
__device__ __half g_wtp[(size_t)EE * EE];           // W_proj^T [768][768]

// ---------------------------------------------------------------------------
// Helpers
// ---------------------------------------------------------------------------
__device__ __forceinline__ uint32_t smem_u32(const void* p) {
    uint32_t a;
    asm("{ .reg .u64 t; cvta.to.shared.u64 t, %1; cvt.u32.u64 %0, t; }"
        : "=r"(a) : "l"(p));
    return a;
}
__device__ __forceinline__ void cp16(uint32_t dst, const void* src) {
    asm volatile("cp.async.cg.shared.global [%0], [%1], 16;"
                 :: "r"(dst), "l"(src) : "memory");
}
__device__ __forceinline__ void cp_commit() {
    asm volatile("cp.async.commit_group;" ::: "memory");
}
template<int N> __device__ __forceinline__ void cp_wait() {
    asm volatile("cp.async.wait_group %0;" :: "n"(N) : "memory");
}
__device__ __forceinline__ uint32_t packh2(float a, float b) {
    __half2 h = __floats2half2_rn(a, b);
    return *(uint32_t*)&h;
}
__device__ __forceinline__ uint32_t ex2_h2(uint32_t x) {   // 2x half exp2, 1 MUFU
    uint32_t r;
    asm("ex2.approx.f16x2 %0, %1;" : "=r"(r) : "r"(x));
    return r;
}
// ldmatrix x4: four 8x8 b16 mats; lane l addresses row l%8 of mat l/8.
__device__ __forceinline__ void ldsm4(uint32_t* r, uint32_t addr) {
    asm volatile("ldmatrix.sync.aligned.m8n8.x4.shared.b16 {%0,%1,%2,%3}, [%4];"
                 : "=r"(r[0]), "=r"(r[1]), "=r"(r[2]), "=r"(r[3]) : "r"(addr));
}
// transposed variant: fragment = transpose of each stored 8x8 (b16)
__device__ __forceinline__ void ldsm4t(uint32_t* r, uint32_t addr) {
    asm volatile("ldmatrix.sync.aligned.m8n8.x4.trans.shared.b16 {%0,%1,%2,%3}, [%4];"
                 : "=r"(r[0]), "=r"(r[1]), "=r"(r[2]), "=r"(r[3]) : "r"(addr));
}

// mma.sync m16n8k16 f16 -> f32.
__device__ __forceinline__ void mma16(float* c, const uint32_t* a,
                                      uint32_t b0, uint32_t b1) {
    asm volatile(
        "mma.sync.aligned.m16n8k16.row.col.f32.f16.f16.f32 "
        "{%0,%1,%2,%3}, {%4,%5,%6,%7}, {%8,%9}, {%0,%1,%2,%3};\n"
        : "+f"(c[0]), "+f"(c[1]), "+f"(c[2]), "+f"(c[3])
        : "r"(a[0]), "r"(a[1]), "r"(a[2]), "r"(a[3]), "r"(b0), "r"(b1));
}

extern __shared__ uint32_t dyn_smem[];

// ---------------------------------------------------------------------------
// Prep kernels
// ---------------------------------------------------------------------------
__global__ __launch_bounds__(256) void cvt_x_kernel(const float* __restrict__ src,
                                                    __half* __restrict__ dst) {
    size_t i = ((size_t)blockIdx.x * 256 + threadIdx.x) * 8;
    float4 v0 = *(const float4*)&src[i];
    float4 v1 = *(const float4*)&src[i + 4];
    uint4 o;
    o.x = packh2(v0.x, v0.y);
    o.y = packh2(v0.z, v0.w);
    o.z = packh2(v1.x, v1.y);
    o.w = packh2(v1.z, v1.w);
    *(uint4*)&dst[i] = o;
}

// dst[n][k] = half(src[k][n])
__global__ __launch_bounds__(256) void transpose_cvt_kernel(
    const float* __restrict__ src, __half* __restrict__ dst, int K, int N)
{
    __shared__ float t[32][33];
    const int n0 = blockIdx.x * 32, k0 = blockIdx.y * 32;
    const int tx = threadIdx.x & 31, ty = threadIdx.x >> 5;   // 32 x 8
#pragma unroll
    for (int j = 0; j < 4; j++)
        t[ty + j * 8][tx] = src[(size_t)(k0 + ty + j * 8) * N + n0 + tx];
    __syncthreads();
#pragma unroll
    for (int j = 0; j < 4; j++)
        dst[(size_t)(n0 + ty + j * 8) * K + k0 + tx] =
            __float2half_rn(t[tx][ty + j * 8]);
}

// ---------------------------------------------------------------------------
// fp16 tensor-core GEMM.  C = A[m][k] @ Bt[n][k]^T + bias.
// Block 128x128, BK=64 halfs, 512 threads = 16 warps (8m x 2n grid of
// m16 x n64 warp tiles — the attention kernel's proven shape).
// cp.async 3-stage single-sync pipeline + REGISTER-level LDSM double
// buffering: ks+1 fragments prefetched during ks mma.
// MODE 0: qkv epilogue staged through smem for coalesced scatter.
// MODE 1: fp32 linear out.
// ---------------------------------------------------------------------------
#define BKH 64
#define NKT (KTOT / BKH)        // 12
#define TILE_W 36
#define HALF_ST (128 * TILE_W)        // words per A (or B) buffer
#define STAGE_WORDS (2 * HALF_ST)     // 9216 words per stage (A then B)
#define GEMM_SMEM (3 * STAGE_WORDS * 4)  // 110592 B
#define CS_HW 136                      // C-stage row stride in halfs

template<int MODE>
__global__ __launch_bounds__(512, 1) void gemm_tc_kernel(
    const __half* __restrict__ A, const __half* __restrict__ Bt,
    const float* __restrict__ bias, float* __restrict__ out)
{
    uint32_t* sm = dyn_smem;
    const uint32_t sb = smem_u32(sm);
    const int tid = threadIdx.x;
    const int warp = tid >> 5, lane = tid & 31;
    const int g = lane >> 2, tg = lane & 3;
    const int wm = warp >> 1, wn = warp & 1;      // 8 x 2 warp grid
    const int m0 = blockIdx.y * 128, n0 = blockIdx.x * 128;
    const int m0w = wm * 16, n0w = wn * 64;

    // cp.async staging: 4 x 16B per thread (2 A + 2 B)
    const int lr = tid >> 2;                 // row 0..127
    const int cb = (tid & 3) * 2;            // chunk pair base (16B chunks)
    const __half* asrc0 = A + (size_t)(m0 + lr) * KTOT + cb * 8;
    const __half* bsrc0 = Bt + (size_t)(n0 + lr) * KTOT + cb * 8;
    const uint32_t adst0 = sb + (lr * TILE_W + cb * 4) * 4;
    const uint32_t bdst0 = sb + (HALF_ST + lr * TILE_W + cb * 4) * 4;

    // LDSM per-lane base offsets (within a stage)
    const int mt = lane >> 3, mr = lane & 7;
    const uint32_t aoff =
        ((m0w + (mt & 1) * 8 + mr) * TILE_W + (mt >> 1) * 4) * 4;
    uint32_t boff[4];
#pragma unroll
    for (int np = 0; np < 4; np++)
        boff[np] = (HALF_ST + (n0w + np * 16 + (mt >> 1) * 8 + mr) * TILE_W
                    + (mt & 1) * 4) * 4;

    float acc[8][4];
#pragma unroll
    for (int nt = 0; nt < 8; nt++)
#pragma unroll
        for (int j = 0; j < 4; j++) acc[nt][j] = 0.f;

    auto issue = [&](int i) {
        const int s = i % 3;
        const int k0 = i * BKH;
        const uint32_t so = (uint32_t)(s * STAGE_WORDS * 4);
        cp16(adst0 + so,      asrc0 + k0);
        cp16(adst0 + so + 16, asrc0 + k0 + 8);
        cp16(bdst0 + so,      bsrc0 + k0);
        cp16(bdst0 + so + 16, bsrc0 + k0 + 8);
        cp_commit();
    };

    issue(0);
    issue(1);
    for (int i = 0; i < NKT; i++) {
        if (i + 1 < NKT) cp_wait<1>(); else cp_wait<0>();
        __syncthreads();
        if (i + 2 < NKT) issue(i + 2);   // writes stage (i-1)%3: readers done

        const uint32_t soff = sb + (uint32_t)((i % 3) * STAGE_WORDS * 4);

        // Register-pipelined fragment loads: prefetch ks+1 during ks mma.
        uint32_t af[2][4], bf[2][4][4];
        ldsm4(af[0], soff + aoff);
#pragma unroll
        for (int np = 0; np < 4; np++) ldsm4(bf[0][np], soff + boff[np]);
#pragma unroll
        for (int ks = 0; ks < 4; ks++) {
            const int cur = ks & 1, nxt = cur ^ 1;
            if (ks < 3) {
                const uint32_t ko = soff + (ks + 1) * 32;
                ldsm4(af[nxt], ko + aoff);
#pragma unroll
                for (int np = 0; np < 4; np++) ldsm4(bf[nxt][np], ko + boff[np]);
            }
#pragma unroll
            for (int np = 0; np < 4; np++) {
                mma16(acc[2 * np],     af[cur], bf[cur][np][0], bf[cur][np][1]);
                mma16(acc[2 * np + 1], af[cur], bf[cur][np][2], bf[cur][np][3]);
            }
        }
    }

    if (MODE == 0) {
        // Stage C (bias+scale, half) into smem, then coalesced scatter.
        __half* Cs = (__half*)sm;
#pragma unroll
        for (int nt = 0; nt < 8; nt++) {
            int lcol = n0w + nt * 8 + 2 * tg;
            int gn = n0 + lcol;
            float b0v = bias[gn], b1v = bias[gn + 1];
            float sc = (gn < EE) ? (0.125f * LOG2E) : 1.0f;
            *(__half2*)&Cs[(m0w + g) * CS_HW + lcol] =
                __floats2half2_rn((acc[nt][0] + b0v) * sc, (acc[nt][1] + b1v) * sc);
            *(__half2*)&Cs[(m0w + 8 + g) * CS_HW + lcol] =
                __floats2half2_rn((acc[nt][2] + b0v) * sc, (acc[nt][3] + b1v) * sc);
        }
        __syncthreads();
#pragma unroll
        for (int it = 0; it < 4; it++) {
            int c = it * 512 + tid;            // 0..2047
            int row = c >> 4, seg = c & 15;    // 16B segments per row
            uint4 v = *(uint4*)&Cs[row * CS_HW + seg * 8];
            int gm = m0 + row, gn = n0 + seg * 8;
            int bbv = gm >> 12, t = gm & (TT - 1);
            int part = gn / EE;
            int rem = gn - part * EE;
            int hh = rem >> 6, d = rem & 63;
            __half* dst = (part == 0) ? g_q : ((part == 1) ? g_k : g_v);
            *(uint4*)&dst[(((size_t)bbv * HH + hh) * TT + t) * DD + d] = v;
        }
    } else {
#pragma unroll
        for (int nt = 0; nt < 8; nt++) {
            int gn = n0 + n0w + nt * 8 + 2 * tg;
            float b0v = bias[gn], b1v = bias[gn + 1];
            int gm0 = m0 + m0w + g;
            *(float2*)&out[(size_t)gm0 * EE + gn] =
                make_float2(acc[nt][0] + b0v, acc[nt][1] + b1v);
            *(float2*)&out[(size_t)(gm0 + 8) * EE + gn] =
                make_float2(acc[nt][2] + b0v, acc[nt][3] + b1v);
        }
    }
}

// ---------------------------------------------------------------------------
// Causal flash attention, fp16 mma + LDSM (V via ldmatrix.trans), f16x2 exp2
// softmax, row-sum via ones-MMA, P in registers.  Grid: (T/128, H, B) heavy
// tiles first, 256 threads (8 warps), warp tile m16 x kv64.  3-stage cp.async
// K/V ring, ONE __syncthreads per kv tile.
// ---------------------------------------------------------------------------
#define AT_W 36
#define QS_WORDS (128 * AT_W)       // 4608
#define KV_WORDS (64 * AT_W)        // 2304
#define STAGE_W (2 * KV_WORDS)      // 4608
#define ATT_SMEM ((QS_WORDS + 3 * STAGE_W) * 4)   // 73728 B
#define ONES_H2 0x3C003C00u

__global__ __launch_bounds__(256, 2) void attn_tc_kernel()
{
    uint32_t* sm = dyn_smem;
    const uint32_t sb = smem_u32(sm);

    const int tid = threadIdx.x;
    const int warp = tid >> 5, lane = tid & 31;
    const int g = lane >> 2, tg = lane & 3;
    const int qt = (TT / 128 - 1) - blockIdx.x;   // heavy (large qt) first
    const int h = blockIdx.y, bb = blockIdx.z;
    const int q0 = qt * 128;

    const size_t hb = (size_t)bb * HH + h;
    const __half* qp = g_q + hb * TT * DD;
    const __half* kp = g_k + hb * TT * DD;
    const __half* vp = g_v + hb * TT * DD;

    // Issue Q tile (128 rows x 64 halfs) -> Qs   [group 0]
#pragma unroll
    for (int i = 0; i < 4; i++) {
        int idx = i * 256 + tid;
        int row = idx >> 3, c = idx & 7;
        cp16(sb + (row * AT_W + c * 4) * 4, qp + (size_t)(q0 + row) * DD + c * 8);
    }
    cp_commit();

    auto issueKV = [&](int kt) {
        const int st = kt % 3;
        const uint32_t base = sb + (QS_WORDS + st * STAGE_W) * 4;
#pragma unroll
        for (int i = 0; i < 4; i++) {
            int idx = i * 256 + tid;
            if (idx < 512) {                    // K rows (kv)
                int row = idx >> 3, c = idx & 7;
                cp16(base + (row * AT_W + c * 4) * 4,
                     kp + (size_t)(kt * 64 + row) * DD + c * 8);
            } else {                            // V rows (kv), same layout
                int j = idx - 512;
                int row = j >> 3, c = j & 7;
                cp16(base + (KV_WORDS + row * AT_W + c * 4) * 4,
                     vp + (size_t)(kt * 64 + row) * DD + c * 8);
            }
        }
        cp_commit();
    };

    const int kt_end = 2 * qt + 1;   // inclusive; >= 1 always
    issueKV(0);
    issueKV(1);

    // Wait for Q (oldest group), build Q fragments with LDSM
    cp_wait<2>();
    __syncthreads();

    const int mt = lane >> 3, mr = lane & 7;
    uint32_t qf[4][4];
    {
        const uint32_t qrow = sb + ((warp * 16 + (mt & 1) * 8 + mr) * AT_W) * 4;
#pragma unroll
        for (int c = 0; c < 4; c++)
            ldsm4(qf[c], qrow + (c * 8 + (mt >> 1) * 4) * 4);
    }
    // K B-frag per-lane offsets (within a K tile): rows = kv (n), cols = d (k)
    uint32_t bofs[4];
#pragma unroll
    for (int np = 0; np < 4; np++)
        bofs[np] = ((np * 16 + (mt >> 1) * 8 + mr) * AT_W + (mt & 1) * 4) * 4;
    // V B-frag per-lane offsets (trans ldsm): rows = kv (k), cols = d (n).
    uint32_t vofs[4];
#pragma unroll
    for (int np = 0; np < 4; np++)
        vofs[np] = (((mt & 1) * 8 + mr) * AT_W + np * 8 + (mt >> 1) * 4) * 4;

    float o[8][4];
    float osum[4] = {0.f, 0.f, 0.f, 0.f};   // P@ones accumulator (row sums)
    float m0_ = -1e30f, m1_ = -1e30f;
#pragma unroll
    for (int nt = 0; nt < 8; nt++)
#pragma unroll
        for (int j = 0; j < 4; j++) o[nt][j] = 0.f;

    for (int kt = 0; kt <= kt_end; kt++) {
        if (kt + 1 <= kt_end) cp_wait<1>(); else cp_wait<0>();
        __syncthreads();
        if (kt + 2 <= kt_end) issueKV(kt + 2);   // stage (kt-1)%3: readers done

        const uint32_t kbase = sb + (QS_WORDS + (kt % 3) * STAGE_W) * 4;
        const uint32_t vbase = kbase + KV_WORDS * 4;

        // S = Q K^T  (16 x 64 per warp), log2-domain scores
        float s[8][4];
#pragma unroll
        for (int nt = 0; nt < 8; nt++)
#pragma unroll
            for (int j = 0; j < 4; j++) s[nt][j] = 0.f;
#pragma unroll
        for (int c = 0; c < 4; c++) {
            uint32_t bf[4][4];
#pragma unroll
            for (int np = 0; np < 4; np++) ldsm4(bf[np], kbase + bofs[np] + c * 32);
#pragma unroll
            for (int np = 0; np < 4; np++) {
                mma16(s[2 * np],     qf[c], bf[np][0], bf[np][1]);
                mma16(s[2 * np + 1], qf[c], bf[np][2], bf[np][3]);
            }
        }

        // Causal mask (diagonal-overlapping tiles only)
        if (kt >= 2 * qt) {
            int row0 = q0 + warp * 16 + g;
#pragma unroll
            for (int nt = 0; nt < 8; nt++) {
                int col = kt * 64 + nt * 8 + 2 * tg;
                if (col > row0)     s[nt][0] = -1e30f;
                if (col + 1 > row0) s[nt][1] = -1e30f;
                if (col > row0 + 8)     s[nt][2] = -1e30f;
                if (col + 1 > row0 + 8) s[nt][3] = -1e30f;
            }
        }

        // Online softmax (base-2): max in f32, exp via f16x2 MUFU.
        float mx0 = -1e30f, mx1 = -1e30f;
#pragma unroll
        for (int nt = 0; nt < 8; nt++) {
            mx0 = fmaxf(mx0, fmaxf(s[nt][0], s[nt][1]));
            mx1 = fmaxf(mx1, fmaxf(s[nt][2], s[nt][3]));
        }
        mx0 = fmaxf(mx0, __shfl_xor_sync(0xffffffffu, mx0, 1));
        mx0 = fmaxf(mx0, __shfl_xor_sync(0xffffffffu, mx0, 2));
        mx1 = fmaxf(mx1, __shfl_xor_sync(0xffffffffu, mx1, 1));
        mx1 = fmaxf(mx1, __shfl_xor_sync(0xffffffffu, mx1, 2));
        float mn0 = fmaxf(m0_, mx0), mn1 = fmaxf(m1_, mx1);
        float f0 = exp2f(m0_ - mn0), f1 = exp2f(m1_ - mn1);
        m0_ = mn0; m1_ = mn1;

        // P = exp2(s - mn) as packed halves == PV A-fragments directly
        uint32_t pe[8][2];
#pragma unroll
        for (int nt = 0; nt < 8; nt++) {
            pe[nt][0] = ex2_h2(packh2(s[nt][0] - mn0, s[nt][1] - mn0));
            pe[nt][1] = ex2_h2(packh2(s[nt][2] - mn1, s[nt][3] - mn1));
        }

        // Rescale running O and row-sum accumulators
#pragma unroll
        for (int nt = 0; nt < 8; nt++) {
            o[nt][0] *= f0; o[nt][1] *= f0;
            o[nt][2] *= f1; o[nt][3] *= f1;
        }
        osum[0] *= f0; osum[1] *= f0; osum[2] *= f1; osum[3] *= f1;

        // O += P V  (+ row sums via ones-column mma)
#pragma unroll
        for (int c = 0; c < 4; c++) {
            uint32_t pa[4] = { pe[2 * c][0], pe[2 * c][1],
                               pe[2 * c + 1][0], pe[2 * c + 1][1] };
            mma16(osum, pa, ONES_H2, ONES_H2);
            uint32_t bf[4][4];
#pragma unroll
            for (int np = 0; np < 4; np++)
                ldsm4t(bf[np], vbase + vofs[np] + c * 16 * AT_W * 4);
#pragma unroll
            for (int np = 0; np < 4; np++) {
                mma16(o[2 * np],     pa, bf[np][0], bf[np][1]);
                mma16(o[2 * np + 1], pa, bf[np][2], bf[np][3]);
            }
        }
    }

    // Normalize, convert, write g_y [B,T,E]
    float inv0 = 1.f / osum[0], inv1 = 1.f / osum[2];
    int t0 = q0 + warp * 16 + g;
#pragma unroll
    for (int nt = 0; nt < 8; nt++) {
        int col = h * 64 + nt * 8 + 2 * tg;
        *(__half2*)&g_y[((size_t)bb * TT + t0) * EE + col] =
            __floats2half2_rn(o[nt][0] * inv0, o[nt][1] * inv0);
        *(__half2*)&g_y[((size_t)bb * TT + t0 + 8) * EE + col] =
            __floats2half2_rn(o[nt][2] * inv1, o[nt][3] * inv1);
    }
}

// ---------------------------------------------------------------------------
extern "C" void kernel_launch(void* const* d_in, const int* in_sizes, int n_in,
                              void* d_out, int out_size)
{
    (void)in_sizes; (void)n_in; (void)out_size;
    const float* x      = (const float*)d_in[0];
    const float* W_attn = (const float*)d_in[1];
    const float* b_attn = (const float*)d_in[2];
    const float* W_proj = (const float*)d_in[3];
    const float* b_proj = (const float*)d_in[4];
    float* out = (float*)d_out;

    __half *xt, *wta, *wtp, *yv;
    cudaGetSymbolAddress((void**)&xt, g_xt);
    cudaGetSymbolAddress((void**)&wta, g_wta);
    cudaGetSymbolAddress((void**)&wtp, g_wtp);
    cudaGetSymbolAddress((void**)&yv, g_y);

    // 0) Convert X to half; transpose + convert weights
    cvt_x_kernel<<<(MM * EE) / (256 * 8), 256>>>(x, xt);
    transpose_cvt_kernel<<<dim3(N_QKV / 32, EE / 32), 256>>>(W_attn, wta, EE, N_QKV);
    transpose_cvt_kernel<<<dim3(EE / 32, EE / 32), 256>>>(W_proj, wtp, EE, EE);

    // 1) QKV projection -> g_q/g_k/g_v (q scaled by 0.125*log2e)
    cudaFuncSetAttribute(gemm_tc_kernel<0>,
                         cudaFuncAttributeMaxDynamicSharedMemorySize, GEMM_SMEM);
    gemm_tc_kernel<0><<<dim3(N_QKV / 128, MM / 128), 512, GEMM_SMEM>>>(
        xt, wta, b_attn, nullptr);

    // 2) Causal flash attention -> g_y
    cudaFuncSetAttribute(attn_tc_kernel,
                         cudaFuncAttributeMaxDynamicSharedMemorySize, ATT_SMEM);
    attn_tc_kernel<<<dim3(TT / 128, HH, BB), 256, ATT_SMEM>>>();

    // 3) Output projection -> d_out (fp32)
    cudaFuncSetAttribute(gemm_tc_kernel<1>,
                         cudaFuncAttributeMaxDynamicSharedMemorySize, GEMM_SMEM);
    gemm_tc_kernel<1><<<dim3(EE / 128, MM / 128), 512, GEMM_SMEM>>>(
        yv, wtp, b_proj, out);
}